// round 13
// baseline (speedup 1.0000x reference)
#include <cuda_runtime.h>
#include <cuda_fp16.h>
#include <math.h>
#include <stdint.h>

#define TS 1024
#define TB 8
#define TE 512
#define TDH 256
#define NTOK 8192

// ---------------- fp32 scratch ----------------
__device__ __align__(16) float g_proj[(size_t)NTOK*TE];
__device__ __align__(16) float g_x1  [(size_t)NTOK*TE];
__device__ __align__(16) float g_lg  [(size_t)NTOK*128];
__device__ __align__(16) float g_x2  [(size_t)NTOK*TE];
__device__ __align__(16) float g_ffo [(size_t)NTOK*TE];
__device__ __align__(16) float g_hb  [256];

// ---------------- fp16 scratch ----------------
__device__ __align__(16) __half h_qkv [(size_t)NTOK*1536];
__device__ __align__(16) __half h_xin [(size_t)NTOK*512];
__device__ __align__(16) __half h_ao  [(size_t)NTOK*512];
__device__ __align__(16) __half h_lg  [(size_t)NTOK*128];
__device__ __align__(16) __half h_x2  [(size_t)NTOK*512];
__device__ __align__(16) __half h_ffh [(size_t)NTOK*2048];
__device__ __align__(16) __half h_hin [(size_t)NTOK*896];
__device__ __align__(16) __half h_lgin[(size_t)NTOK*768];
__device__ __align__(16) __half h_w1  [1536*512];
__device__ __align__(16) __half h_w2  [512*512];
__device__ __align__(16) __half h_uw  [512*128];
__device__ __align__(16) __half h_w3  [2048*512];
__device__ __align__(16) __half h_w4  [512*2048];
__device__ __align__(16) __half h_hw  [256*896];
__device__ __align__(16) __half h_vw  [128*768];

__device__ __forceinline__ float nonsat_f(float x) {
    float y = x;
#pragma unroll 1
    for (int it = 0; it < 32; ++it) {
        float y2 = y * y;
        float yn = __fdividef(0.66666668f * y * y2 + x, y2 + 1.0f);
        float d = fabsf(yn - y);
        y = yn;
        if (d <= 1e-6f) break;
    }
    return y;
}

__device__ __forceinline__ uint32_t su32(const void* p) {
    uint32_t a;
    asm("{ .reg .u64 t; cvta.to.shared.u64 t, %1; cvt.u32.u64 %0, t; }" : "=r"(a) : "l"(p));
    return a;
}
__device__ __forceinline__ void cp16(uint32_t s, const void* g) {
    asm volatile("cp.async.cg.shared.global [%0], [%1], 16;"
                 :: "r"(s), "l"(__cvta_generic_to_global(g)) : "memory");
}
__device__ __forceinline__ void cp_commit() {
    asm volatile("cp.async.commit_group;" ::: "memory");
}
template<int N> __device__ __forceinline__ void cp_wait() {
    asm volatile("cp.async.wait_group %0;" :: "n"(N) : "memory");
}
__device__ __forceinline__ void ldmx4(uint32_t* r, uint32_t addr) {
    asm volatile("ldmatrix.sync.aligned.m8n8.x4.shared.b16 {%0,%1,%2,%3}, [%4];"
        : "=r"(r[0]), "=r"(r[1]), "=r"(r[2]), "=r"(r[3]) : "r"(addr));
}
__device__ __forceinline__ void ldmx4t(uint32_t* r, uint32_t addr) {
    asm volatile("ldmatrix.sync.aligned.m8n8.x4.trans.shared.b16 {%0,%1,%2,%3}, [%4];"
        : "=r"(r[0]), "=r"(r[1]), "=r"(r[2]), "=r"(r[3]) : "r"(addr));
}
__device__ __forceinline__ void mma16816(float* c, const uint32_t* a, const uint32_t* b) {
    asm volatile(
        "mma.sync.aligned.m16n8k16.row.col.f32.f16.f16.f32 "
        "{%0,%1,%2,%3}, {%4,%5,%6,%7}, {%8,%9}, {%0,%1,%2,%3};\n"
        : "+f"(c[0]), "+f"(c[1]), "+f"(c[2]), "+f"(c[3])
        : "r"(a[0]), "r"(a[1]), "r"(a[2]), "r"(a[3]), "r"(b[0]), "r"(b[1]));
}
__device__ __forceinline__ uint32_t pkh2(float lo, float hi) {
    __half2 h = __floats2half2_rn(lo, hi);
    return *(uint32_t*)&h;
}
__device__ __forceinline__ void store_h2(__half* H, size_t idx, float a, float b) {
    *(__half2*)(H + idx) = __floats2half2_rn(a, b);
}

// ---------------- merged fp32->fp16 convert (weights + x_in, 1 launch) ----------------
#define SEG0 196608
#define SEG1 262144
#define SEG2 278528
#define SEG3 540672
#define SEG4 802816
#define SEG5 827392
#define SEGT 1875968

__global__ void __launch_bounds__(256) cvt_all_kernel(
    const float* __restrict__ s0, const float* __restrict__ s1,
    const float* __restrict__ s2, const float* __restrict__ s3,
    const float* __restrict__ s4, const float* __restrict__ s5,
    const float* __restrict__ s6)
{
    int i = blockIdx.x * 256 + threadIdx.x;
    if (i >= SEGT) return;
    const float* src; __half* dst; int rel;
    if (i < SEG0)      { src = s0; dst = h_w1; rel = i; }
    else if (i < SEG1) { src = s1; dst = h_w2; rel = i - SEG0; }
    else if (i < SEG2) { src = s2; dst = h_uw; rel = i - SEG1; }
    else if (i < SEG3) { src = s3; dst = h_w3; rel = i - SEG2; }
    else if (i < SEG4) { src = s4; dst = h_w4; rel = i - SEG3; }
    else if (i < SEG5) { src = s5; dst = h_vw; rel = i - SEG4; }
    else               { src = s6; dst = h_xin; rel = i - SEG5; }
    float4 v = ((const float4*)src)[rel];
    ((__half2*)dst)[2*rel]   = __floats2half2_rn(v.x, v.y);
    ((__half2*)dst)[2*rel+1] = __floats2half2_rn(v.z, v.w);
}

// pack hidden-GEMM input: row u = [x1(perm) | hidden_prev | stack_top | 0pad], K=896
__global__ void __launch_bounds__(256) pack_hidden_in(
    const float* __restrict__ x1, const float* __restrict__ hp,
    const float* __restrict__ sp, __half* __restrict__ H)
{
    int idx = blockIdx.x * 256 + threadIdx.x;
    if (idx >= NTOK * 448) return;
    int u = idx / 448, col = (idx % 448) << 1;
    float a = 0.f, b = 0.f;
    if (col < 512) {
        int tp = ((u & 1023) << 3) | (u >> 10);
        float2 v = *(const float2*)(x1 + (size_t)tp * 512 + col);
        a = v.x; b = v.y;
    } else if (col < 768) {
        float2 v = *(const float2*)(hp + (size_t)u * 256 + col - 512);
        a = v.x; b = v.y;
    } else if (col < 864) {
        float2 v = *(const float2*)(sp + (size_t)u * 4608 + col - 768);
        a = v.x; b = v.y;
    }
    store_h2(H, (size_t)u * 896 + col, a, b);
}

__global__ void __launch_bounds__(256) pack_hw(
    const float* __restrict__ Ww, const float* __restrict__ Rw, const float* __restrict__ Pw,
    const float* __restrict__ Wb, const float* __restrict__ Rb, const float* __restrict__ Pb,
    __half* __restrict__ H, float* __restrict__ bsum)
{
    int idx = blockIdx.x * 256 + threadIdx.x;
    if (idx < 256) bsum[idx] = Wb[idx] + Rb[idx] + Pb[idx];
    if (idx >= 256 * 448) return;
    int n = idx / 448, col = (idx % 448) << 1;
    float a = 0.f, b = 0.f;
    if (col < 512) {
        float2 v = *(const float2*)(Ww + (size_t)n * 512 + col);
        a = v.x; b = v.y;
    } else if (col < 768) {
        float2 v = *(const float2*)(Rw + (size_t)n * 256 + col - 512);
        a = v.x; b = v.y;
    } else if (col < 864) {
        float2 v = *(const float2*)(Pw + (size_t)n * 96 + col - 768);
        a = v.x; b = v.y;
    }
    store_h2(H, (size_t)n * 896 + col, a, b);
}

__global__ void __launch_bounds__(256) pack_logits_in(
    const float* __restrict__ x1, const float* __restrict__ hid, __half* __restrict__ H)
{
    int idx = blockIdx.x * 256 + threadIdx.x;
    if (idx >= NTOK * 384) return;
    int t = idx / 384, col = (idx % 384) << 1;
    float a, b;
    if (col < 512) {
        float2 v = *(const float2*)(x1 + (size_t)t * 512 + col);
        a = v.x; b = v.y;
    } else {
        int up = ((t & 7) << 10) | (t >> 3);
        float2 v = *(const float2*)(hid + (size_t)up * 256 + col - 512);
        a = v.x; b = v.y;
    }
    store_h2(H, (size_t)t * 768 + col, a, b);
}

// ---------------- fp16 HMMA GEMM: 4 warps, warp tile 64x64, cp.async 2-stage ----------------
// stage: A 0 (16KB), B 16384 (16KB); stage 32KB, total 64KB
#define T_A 0
#define T_B 16384
#define T_STAGE 32768
#define T_SMEM  65536

template<int EPI, int OUT>
__global__ void __launch_bounds__(128) tgemm(
    const __half* __restrict__ A, const __half* __restrict__ W,
    const float* __restrict__ bias, const float* __restrict__ res,
    float* __restrict__ C, __half* __restrict__ Ch,
    int M, int N, int K)
{
    extern __shared__ char smem[];
    const uint32_t sbase = su32(smem);
    const int tid = threadIdx.x, wid = tid >> 5, lane = tid & 31;
    const int m0 = blockIdx.y * 128, n0 = blockIdx.x * 128;
    const int g = lane >> 2, t2 = (lane & 3) << 1;
    const int wr = (wid & 1) << 6;
    const int wc = (wid >> 1) << 6;
    const int l7 = lane & 7, lr15 = lane & 15;
    const uint32_t swz = (uint32_t)(l7 << 4);
    const int aklo = (lane >> 4) << 3;
    const int bklo = ((lane >> 3) & 1) << 3;
    const uint32_t arow = (uint32_t)((wr + lr15) << 7);
    const uint32_t brow = (uint32_t)((wc + l7 + ((lane >> 4) << 3)) << 7);

    uint32_t soff[8], gaoff[8], gboff[8];
#pragma unroll
    for (int t = 0; t < 8; t++) {
        int e = tid + (t << 7);
        int r = e >> 3, q = e & 7;
        uint32_t off = (uint32_t)((r << 7) + (q << 4));
        off ^= (off >> 3) & 0x70;
        soff[t] = off;
        gaoff[t] = (uint32_t)((m0 + r) * K + (q << 3));
        gboff[t] = (uint32_t)((n0 + r) * K + (q << 3));
    }

    float c[4][8][4];
#pragma unroll
    for (int i = 0; i < 4; i++)
#pragma unroll
        for (int j = 0; j < 8; j++)
#pragma unroll
            for (int q = 0; q < 4; q++) c[i][j][q] = 0.f;

    const int nch = K >> 6;

#define ISSUE_CHUNK(CH, BUF) do { \
    const int k0_ = (CH) << 6; \
    const uint32_t sb_ = sbase + (BUF) * T_STAGE; \
    for (int t_ = 0; t_ < 8; t_++) { \
        cp16(sb_ + T_A + soff[t_], A + gaoff[t_] + k0_); \
        cp16(sb_ + T_B + soff[t_], W + gboff[t_] + k0_); \
    } \
    cp_commit(); \
} while (0)

    ISSUE_CHUNK(0, 0);
    for (int ch = 0; ch < nch; ch++) {
        if (ch + 1 < nch) { ISSUE_CHUNK(ch + 1, (ch + 1) & 1); cp_wait<1>(); }
        else cp_wait<0>();
        __syncthreads();
        const uint32_t bb = sbase + (ch & 1) * T_STAGE;
#pragma unroll
        for (int kk = 0; kk < 64; kk += 16) {
            uint32_t bf[4][4];
            const uint32_t boff = ((uint32_t)((kk + bklo) << 1)) ^ swz;
#pragma unroll
            for (int bi = 0; bi < 4; bi++)
                ldmx4(bf[bi], bb + T_B + brow + (uint32_t)(bi << 11) + boff);
            const uint32_t aoff = ((uint32_t)((kk + aklo) << 1)) ^ swz;
#pragma unroll
            for (int mi = 0; mi < 4; mi++) {
                uint32_t af[4];
                ldmx4(af, bb + T_A + arow + (uint32_t)(mi << 11) + aoff);
#pragma unroll
                for (int bi = 0; bi < 4; bi++) {
                    mma16816(c[mi][2*bi],   af, &bf[bi][0]);
                    mma16816(c[mi][2*bi+1], af, &bf[bi][2]);
                }
            }
        }
        __syncthreads();
    }
#undef ISSUE_CHUNK

#pragma unroll
    for (int mi = 0; mi < 4; mi++) {
#pragma unroll
        for (int ni = 0; ni < 8; ni++) {
            int row = m0 + wr + (mi << 4) + g;
            int col = n0 + wc + (ni << 3) + t2;
#pragma unroll
            for (int h = 0; h < 2; h++) {
                int rr = row + h * 8;
                float v0 = c[mi][ni][2 * h], v1 = c[mi][ni][2 * h + 1];
                if (EPI == 0) {
                    v0 += bias[col]; v1 += bias[col + 1];
                } else if (EPI == 1) {
                    v0 = nonsat_f(v0 + bias[col]); v1 = nonsat_f(v1 + bias[col + 1]);
                } else if (EPI == 2) {
                    const float2 rv = *(const float2*)(res + (size_t)rr * N + col);
                    v0 = 0.5f * (v0 + rv.x); v1 = 0.5f * (v1 + rv.y);
                }
                if (OUT == 0 || OUT == 2) {
                    float2 o; o.x = v0; o.y = v1;
                    *(float2*)(C + (size_t)rr * N + col) = o;
                }
                if (OUT == 1 || OUT == 2) {
                    store_h2(Ch, (size_t)rr * N + col, v0, v1);
                }
            }
        }
    }
}

// ---------------- fp16 HMMA flash attention: 128 q-rows/CTA, cp.async 2-stage ----------------
// smem: Q 0 (16KB); stage s at 16384 + s*16384 {K+0 (8KB), V+8192 (8KB)}
#define A_SMEM 49152

__global__ void __launch_bounds__(256) attn_kernel(
    const __half* __restrict__ Q, __half* __restrict__ ao)
{
    extern __shared__ char sm[];
    const int qt = blockIdx.x, q0 = qt << 7;
    const int b = blockIdx.y >> 3, h = blockIdx.y & 7;
    const int tid = threadIdx.x, wid = tid >> 5, lane = tid & 31;
    const int g = lane >> 2, t2 = (lane & 3) << 1;
    const uint32_t sbase = su32(sm);
    const int l7 = lane & 7, lr15 = lane & 15;
    const uint32_t swz = (uint32_t)(l7 << 4);
    const int klo8 = (lane >> 4) << 3;
    const int bk8 = ((lane >> 3) & 1) << 3;
    const int wq = wid << 4;

    uint32_t qoff[4]; int qrow[4], qq8[4];
#pragma unroll
    for (int t = 0; t < 4; t++) {
        int e = tid + (t << 8);
        int r = e >> 3, q = e & 7;
        uint32_t off = (uint32_t)((r << 7) + (q << 4));
        off ^= (off >> 3) & 0x70;
        qoff[t] = off; qrow[t] = r; qq8[t] = q << 3;
    }

    const size_t qbase = ((size_t)q0 * TB + b) * 1536 + h * 64;
#pragma unroll
    for (int t = 0; t < 4; t++) {
        const size_t gs = qbase + (size_t)qrow[t] * (TB * 1536) + qq8[t];
        cp16(sbase + qoff[t], Q + gs);
    }
#define ISSUE_KV(KT, BUF) do { \
    const size_t kb_ = ((size_t)((KT) << 6) * TB + b) * 1536 + h * 64; \
    const uint32_t st_ = sbase + 16384 + (BUF) * 16384; \
    for (int t_ = 0; t_ < 2; t_++) { \
        const size_t gk_ = kb_ + (size_t)qrow[t_] * (TB * 1536) + 512 + qq8[t_]; \
        const size_t gv_ = kb_ + (size_t)qrow[t_] * (TB * 1536) + 1024 + qq8[t_]; \
        cp16(st_ + 0    + qoff[t_], Q + gk_); \
        cp16(st_ + 8192 + qoff[t_], Q + gv_); \
    } \
    cp_commit(); \
} while (0)
    ISSUE_KV(0, 0);

    float o[8][4];
#pragma unroll
    for (int i = 0; i < 8; i++)
#pragma unroll
        for (int j = 0; j < 4; j++) o[i][j] = 0.f;
    float m0 = -1e30f, m1 = -1e30f, l0 = 0.f, l1 = 0.f;

    const uint32_t aA = sbase + (uint32_t)((wq + lr15) << 7);
    const uint32_t brel = (uint32_t)((l7 + ((lane >> 4) << 3)) << 7);
    const uint32_t vrel = (uint32_t)((l7 + (((lane >> 3) & 1) << 3)) << 7);

    const int ntiles = (qt << 1) + 2;
    for (int kt = 0; kt < ntiles; kt++) {
        const int kv0 = kt << 6;
        if (kt + 1 < ntiles) { ISSUE_KV(kt + 1, (kt + 1) & 1); cp_wait<1>(); }
        else cp_wait<0>();
        __syncthreads();
        const uint32_t st = sbase + 16384 + (kt & 1) * 16384;

        float sc[8][4];
#pragma unroll
        for (int i = 0; i < 8; i++)
#pragma unroll
            for (int j = 0; j < 4; j++) sc[i][j] = 0.f;
#pragma unroll
        for (int kk = 0; kk < 64; kk += 16) {
            uint32_t qf[4];
            const uint32_t aoff = ((uint32_t)((kk + klo8) << 1)) ^ swz;
            ldmx4(qf, aA + aoff);
            const uint32_t boff = ((uint32_t)((kk + bk8) << 1)) ^ swz;
#pragma unroll
            for (int bi = 0; bi < 4; bi++) {
                uint32_t kf[4];
                ldmx4(kf, st + brel + (uint32_t)(bi << 11) + boff);
                mma16816(sc[2*bi],   qf, &kf[0]);
                mma16816(sc[2*bi+1], qf, &kf[2]);
            }
        }

        const int r0 = q0 + wq + g, r1 = r0 + 8;
        const bool diag = (kv0 + 63 > r0);
        float tm0 = -1e30f, tm1 = -1e30f;
#pragma unroll
        for (int ni = 0; ni < 8; ni++) {
            const int cb = kv0 + (ni << 3) + t2;
            float s0 = sc[ni][0] * 0.125f, s1 = sc[ni][1] * 0.125f;
            float s2 = sc[ni][2] * 0.125f, s3 = sc[ni][3] * 0.125f;
            if (diag) {
                if (cb     > r0) s0 = -1e30f;
                if (cb + 1 > r0) s1 = -1e30f;
                if (cb     > r1) s2 = -1e30f;
                if (cb + 1 > r1) s3 = -1e30f;
            }
            sc[ni][0] = s0; sc[ni][1] = s1; sc[ni][2] = s2; sc[ni][3] = s3;
            tm0 = fmaxf(tm0, fmaxf(s0, s1));
            tm1 = fmaxf(tm1, fmaxf(s2, s3));
        }
        tm0 = fmaxf(tm0, __shfl_xor_sync(0xffffffffu, tm0, 1));
        tm0 = fmaxf(tm0, __shfl_xor_sync(0xffffffffu, tm0, 2));
        tm1 = fmaxf(tm1, __shfl_xor_sync(0xffffffffu, tm1, 1));
        tm1 = fmaxf(tm1, __shfl_xor_sync(0xffffffffu, tm1, 2));
        const float mn0 = fmaxf(m0, tm0), mn1 = fmaxf(m1, tm1);
        const float al0 = __expf(m0 - mn0), al1 = __expf(m1 - mn1);
        m0 = mn0; m1 = mn1;
        float ps0 = 0.f, ps1 = 0.f;
#pragma unroll
        for (int ni = 0; ni < 8; ni++) {
            float p0 = __expf(sc[ni][0] - m0), p1 = __expf(sc[ni][1] - m0);
            float p2 = __expf(sc[ni][2] - m1), p3 = __expf(sc[ni][3] - m1);
            sc[ni][0] = p0; sc[ni][1] = p1; sc[ni][2] = p2; sc[ni][3] = p3;
            ps0 += p0 + p1; ps1 += p2 + p3;
        }
        ps0 += __shfl_xor_sync(0xffffffffu, ps0, 1);
        ps0 += __shfl_xor_sync(0xffffffffu, ps0, 2);
        ps1 += __shfl_xor_sync(0xffffffffu, ps1, 1);
        ps1 += __shfl_xor_sync(0xffffffffu, ps1, 2);
        l0 = l0 * al0 + ps0;
        l1 = l1 * al1 + ps1;
#pragma unroll
        for (int ni = 0; ni < 8; ni++) {
            o[ni][0] *= al0; o[ni][1] *= al0;
            o[ni][2] *= al1; o[ni][3] *= al1;
        }

#pragma unroll
        for (int j = 0; j < 4; j++) {
            uint32_t pa[4];
            pa[0] = pkh2(sc[2*j][0],   sc[2*j][1]);
            pa[1] = pkh2(sc[2*j][2],   sc[2*j][3]);
            pa[2] = pkh2(sc[2*j+1][0], sc[2*j+1][1]);
            pa[3] = pkh2(sc[2*j+1][2], sc[2*j+1][3]);
#pragma unroll
            for (int i = 0; i < 4; i++) {
                uint32_t vf[4];
                const uint32_t voff = (uint32_t)(j << 11) +
                    (((uint32_t)(((i << 4) + klo8) << 1)) ^ swz);
                ldmx4t(vf, st + 8192 + vrel + voff);
                mma16816(o[2*i],   pa, &vf[0]);
                mma16816(o[2*i+1], pa, &vf[2]);
            }
        }
        __syncthreads();
    }
#undef ISSUE_KV

    const float inv0 = __fdividef(1.f, l0), inv1 = __fdividef(1.f, l1);
    const int qg0 = q0 + wq + g;
    const size_t dst0 = ((size_t)qg0 * TB + b) * 512 + h * 64 + t2;
    const size_t dst1 = dst0 + (size_t)8 * TB * 512;
#pragma unroll
    for (int ni = 0; ni < 8; ni++) {
        const int d = ni << 3;
        store_h2(ao, dst0 + d, o[ni][0] * inv0, o[ni][1] * inv0);
        store_h2(ao, dst1 + d, o[ni][2] * inv1, o[ni][3] * inv1);
    }
}

template<bool NS>
__global__ void __launch_bounds__(256) add_ln_kernel(
    const float* __restrict__ xa, const float* __restrict__ xb,
    const float* __restrict__ g, const float* __restrict__ bl,
    float* __restrict__ out)
{
    const int t = blockIdx.x, tid = threadIdx.x;
    __shared__ float red[8];
    const size_t base = (size_t)t * TE;
    float v0 = xa[base+tid] + xb[base+tid];
    float v1 = xa[base+tid+256] + xb[base+tid+256];
    float s = v0 + v1;
#pragma unroll
    for (int o = 16; o; o >>= 1) s += __shfl_xor_sync(0xffffffffu, s, o);
    if ((tid & 31) == 0) red[tid>>5] = s;
    __syncthreads();
    if (tid == 0) { float tt=0; for (int w=0;w<8;w++) tt+=red[w]; red[0]=tt; }
    __syncthreads();
    const float mean = red[0] * (1.0f/512.0f);
    __syncthreads();
    float d0 = v0-mean, d1 = v1-mean;
    float q = d0*d0 + d1*d1;
#pragma unroll
    for (int o = 16; o; o >>= 1) q += __shfl_xor_sync(0xffffffffu, q, o);
    if ((tid & 31) == 0) red[tid>>5] = q;
    __syncthreads();
    if (tid == 0) { float tt=0; for (int w=0;w<8;w++) tt+=red[w]; red[0]=tt; }
    __syncthreads();
    const float rs = rsqrtf(red[0]*(1.0f/512.0f) + 1e-5f);
    float o0 = d0*rs*g[tid]     + bl[tid];
    float o1 = d1*rs*g[tid+256] + bl[tid+256];
    if (NS) { o0 = nonsat_f(o0); o1 = nonsat_f(o1); }
    out[base+tid] = o0;
    out[base+tid+256] = o1;
}

__global__ void __launch_bounds__(256) softmax128_kernel(
    const float* __restrict__ lg, __half* __restrict__ H)
{
    const int t = blockIdx.x * 8 + (threadIdx.x >> 5);
    const int lane = threadIdx.x & 31;
    float4 v = *((const float4*)(lg + (size_t)t * 128) + lane);
    float mx = fmaxf(fmaxf(v.x, v.y), fmaxf(v.z, v.w));
#pragma unroll
    for (int o = 16; o; o >>= 1) mx = fmaxf(mx, __shfl_xor_sync(0xffffffffu, mx, o));
    v.x = __expf(v.x-mx); v.y = __expf(v.y-mx); v.z = __expf(v.z-mx); v.w = __expf(v.w-mx);
    float s = v.x + v.y + v.z + v.w;
#pragma unroll
    for (int o = 16; o; o >>= 1) s += __shfl_xor_sync(0xffffffffu, s, o);
    float is = __fdividef(1.f, s);
    const size_t base = (size_t)t * 128 + (lane << 2);
    store_h2(H, base,     v.x * is, v.y * is);
    store_h2(H, base + 2, v.z * is, v.w * is);
}

__global__ void __launch_bounds__(128) stack_kernel(
    const float* __restrict__ hidden, const float* __restrict__ sp,
    const float* __restrict__ Aw, const float* __restrict__ Ab,
    const float* __restrict__ Dw, const float* __restrict__ Db,
    float* __restrict__ out)
{
    __shared__ __align__(16) float h[256];
    __shared__ __align__(16) float inp[96];
    __shared__ float ctl[3];
    const int u = blockIdx.x, tid = threadIdx.x;
    const float* hrow = hidden + (size_t)u * 256;
    h[tid] = hrow[tid]; h[tid+128] = hrow[tid+128];
    __syncthreads();
    if (tid < 96) {
        const float* w = Dw + tid * 256;
        float s = Db[tid];
        for (int k = 0; k < 256; k += 4) {
            float4 wv = *(const float4*)(w + k);
            s += wv.x*h[k] + wv.y*h[k+1] + wv.z*h[k+2] + wv.w*h[k+3];
        }
        inp[tid] = nonsat_f(s);
    } else if (tid < 99) {
        int i = tid - 96;
        const float* w = Aw + i * 256;
        float s = Ab[i];
        for (int k = 0; k < 256; k++) s += w[k]*h[k];
        ctl[i] = s;
    }
    __syncthreads();
    float mx = fmaxf(ctl[0], fmaxf(ctl[1], ctl[2]));
    float e0 = __expf(ctl[0]-mx), e1 = __expf(ctl[1]-mx), e2 = __expf(ctl[2]-mx);
    float is = __fdividef(1.f, e0+e1+e2);
    float c0 = e0*is, c1 = e1*is, c2 = e2*is;
    const float4* prev = (const float4*)(sp + (size_t)u * 4608);
    float4* dst = (float4*)(out + (size_t)u * 4608);
    const float4* inp4 = (const float4*)inp;
    for (int idx = tid; idx < 1152; idx += 128) {
        int d = idx / 24;
        float4 p = prev[idx];
        float4 up = (d == 0) ? inp4[idx] : prev[idx-24];
        float4 dn;
        if (d == 47) { dn.x=dn.y=dn.z=dn.w=0.f; } else dn = prev[idx+24];
        float4 o;
        o.x = c2*p.x + c0*up.x + c1*dn.x;
        o.y = c2*p.y + c0*up.y + c1*dn.y;
        o.z = c2*p.z + c0*up.z + c1*dn.z;
        o.w = c2*p.w + c0*up.w + c1*dn.w;
        dst[idx] = o;
    }
}

extern "C" void kernel_launch(void* const* d_in, const int* in_sizes, int n_in,
                              void* d_out, int out_size) {
    const float* x_in = (const float*)d_in[0];
    const float* hidden_prev = (const float*)d_in[1];
    const float* stack_prev  = (const float*)d_in[2];
    const float* in_proj_w = (const float*)d_in[3];
    const float* in_proj_b = (const float*)d_in[4];
    const float* out_proj_w = (const float*)d_in[5];
    const float* out_proj_b = (const float*)d_in[6];
    const float* ln1_g = (const float*)d_in[7];
    const float* ln1_b = (const float*)d_in[8];
    const float* ln2_g = (const float*)d_in[9];
    const float* ln2_b = (const float*)d_in[10];
    const float* W_w = (const float*)d_in[11];
    const float* W_b = (const float*)d_in[12];
    const float* R_w = (const float*)d_in[13];
    const float* R_b = (const float*)d_in[14];
    const float* P_w = (const float*)d_in[15];
    const float* P_b = (const float*)d_in[16];
    const float* V_w = (const float*)d_in[17];
    const float* U_w = (const float*)d_in[18];
    const float* A_w = (const float*)d_in[19];
    const float* A_b = (const float*)d_in[20];
    const float* D_w = (const float*)d_in[21];
    const float* D_b = (const float*)d_in[22];
    const float* ffi_w = (const float*)d_in[23];
    const float* ffi_b = (const float*)d_in[24];
    const float* ffo_w = (const float*)d_in[25];
    const float* ffo_b = (const float*)d_in[26];

    static bool init_done = false;
    static float *p_proj,*p_x1,*p_lg,*p_x2,*p_ffo,*p_hb;
    static __half *ph_qkv,*ph_xin,*ph_ao,*ph_lg,*ph_x2,*ph_ffh,*ph_hin,*ph_lgin;
    static __half *ph_w1,*ph_w2,*ph_uw,*ph_w3,*ph_w4,*ph_hw,*ph_vw;
    if (!init_done) {
        cudaGetSymbolAddress((void**)&p_proj, g_proj);
        cudaGetSymbolAddress((void**)&p_x1,   g_x1);
        cudaGetSymbolAddress((void**)&p_lg,   g_lg);
        cudaGetSymbolAddress((void**)&p_x2,   g_x2);
        cudaGetSymbolAddress((void**)&p_ffo,  g_ffo);
        cudaGetSymbolAddress((void**)&p_hb,   g_hb);
        cudaGetSymbolAddress((void**)&ph_qkv,  h_qkv);
        cudaGetSymbolAddress((void**)&ph_xin,  h_xin);
        cudaGetSymbolAddress((void**)&ph_ao,   h_ao);
        cudaGetSymbolAddress((void**)&ph_lg,   h_lg);
        cudaGetSymbolAddress((void**)&ph_x2,   h_x2);
        cudaGetSymbolAddress((void**)&ph_ffh,  h_ffh);
        cudaGetSymbolAddress((void**)&ph_hin,  h_hin);
        cudaGetSymbolAddress((void**)&ph_lgin, h_lgin);
        cudaGetSymbolAddress((void**)&ph_w1,   h_w1);
        cudaGetSymbolAddress((void**)&ph_w2,   h_w2);
        cudaGetSymbolAddress((void**)&ph_uw,   h_uw);
        cudaGetSymbolAddress((void**)&ph_w3,   h_w3);
        cudaGetSymbolAddress((void**)&ph_w4,   h_w4);
        cudaGetSymbolAddress((void**)&ph_hw,   h_hw);
        cudaGetSymbolAddress((void**)&ph_vw,   h_vw);
        cudaFuncSetAttribute(tgemm<0,0>, cudaFuncAttributeMaxDynamicSharedMemorySize, T_SMEM);
        cudaFuncSetAttribute(tgemm<0,1>, cudaFuncAttributeMaxDynamicSharedMemorySize, T_SMEM);
        cudaFuncSetAttribute(tgemm<1,0>, cudaFuncAttributeMaxDynamicSharedMemorySize, T_SMEM);
        cudaFuncSetAttribute(tgemm<1,1>, cudaFuncAttributeMaxDynamicSharedMemorySize, T_SMEM);
        cudaFuncSetAttribute(tgemm<2,2>, cudaFuncAttributeMaxDynamicSharedMemorySize, T_SMEM);
        cudaFuncSetAttribute(tgemm<3,0>, cudaFuncAttributeMaxDynamicSharedMemorySize, T_SMEM);
        cudaFuncSetAttribute(attn_kernel, cudaFuncAttributeMaxDynamicSharedMemorySize, A_SMEM);
        init_done = true;
    }

    float* out_x = (float*)d_out;
    float* out_hidden = out_x + (size_t)NTOK * TE;
    float* out_stack  = out_hidden + (size_t)NTOK * TDH;

    // single batched convert (6 weights + x_in) + hidden weight pack
    cvt_all_kernel<<<(SEGT + 255)/256, 256>>>(in_proj_w, out_proj_w, U_w,
                                              ffi_w, ffo_w, V_w, x_in);
    pack_hw<<<(256*448 + 255)/256, 256>>>(W_w, R_w, P_w, W_b, R_b, P_b, ph_hw, p_hb);

    // 1) qkv (fp16 out)
    tgemm<0,1><<<dim3(12,64),128,T_SMEM>>>(ph_xin, ph_w1,
        in_proj_b, nullptr, nullptr, ph_qkv, NTOK, 1536, 512);
    // 2) flash attention (128 q-rows per CTA)
    attn_kernel<<<dim3(8,64),256,A_SMEM>>>(ph_qkv, ph_ao);
    // 3) out projection
    tgemm<0,0><<<dim3(4,64),128,T_SMEM>>>(ph_ao, ph_w2,
        out_proj_b, nullptr, p_proj, nullptr, NTOK, 512, 512);
    // 4) x1 = nonsat(LN(x_in + proj))
    add_ln_kernel<true><<<NTOK,256>>>(x_in, p_proj, ln1_g, ln1_b, p_x1);
    // 5) hidden via HMMA
    pack_hidden_in<<<(NTOK*448 + 255)/256, 256>>>(p_x1, hidden_prev, stack_prev, ph_hin);
    tgemm<1,0><<<dim3(2,64),128,T_SMEM>>>(ph_hin, ph_hw,
        p_hb, nullptr, out_hidden, nullptr, NTOK, 256, 896);
    // 6) logits via HMMA
    pack_logits_in<<<(NTOK*384 + 255)/256, 256>>>(p_x1, out_hidden, ph_lgin);
    tgemm<3,0><<<dim3(1,64),128,T_SMEM>>>(ph_lgin, ph_vw,
        nullptr, nullptr, p_lg, nullptr, NTOK, 128, 768);
    // 7) softmax (fp16 out)
    softmax128_kernel<<<NTOK/8,256>>>(p_lg, ph_lg);
    // 8) x2 = 0.5*(x1 + sm @ U_w.T)   (fp32 + fp16 out)
    tgemm<2,2><<<dim3(4,64),128,T_SMEM>>>(ph_lg, ph_uw,
        nullptr, p_x1, p_x2, ph_x2, NTOK, 512, 128);
    // 9) stack
    stack_kernel<<<NTOK,128>>>(out_hidden, stack_prev, A_w, A_b, D_w, D_b, out_stack);
    // 10) ff hidden (fp16 out)
    tgemm<1,1><<<dim3(16,64),128,T_SMEM>>>(ph_x2, ph_w3,
        ffi_b, nullptr, nullptr, ph_ffh, NTOK, 2048, 512);
    // 11) ff out
    tgemm<0,0><<<dim3(4,64),128,T_SMEM>>>(ph_ffh, ph_w4,
        ffo_b, nullptr, p_ffo, nullptr, NTOK, 512, 2048);
    // 12) x_out
    add_ln_kernel<false><<<NTOK,256>>>(p_x2, p_ffo, ln2_g, ln2_b, out_x);
}

// round 14
// speedup vs baseline: 1.0631x; 1.0631x over previous
#include <cuda_runtime.h>
#include <cuda_fp16.h>
#include <math.h>
#include <stdint.h>

#define TS 1024
#define TB 8
#define TE 512
#define TDH 256
#define NTOK 8192

// ---------------- fp32 scratch ----------------
__device__ __align__(16) float g_proj[(size_t)NTOK*TE];
__device__ __align__(16) float g_x1  [(size_t)NTOK*TE];
__device__ __align__(16) float g_lg  [(size_t)NTOK*128];
__device__ __align__(16) float g_x2  [(size_t)NTOK*TE];
__device__ __align__(16) float g_ffo [(size_t)NTOK*TE];
__device__ __align__(16) float g_hb  [256];

// ---------------- fp16 scratch ----------------
__device__ __align__(16) __half h_qkv [(size_t)NTOK*1536];
__device__ __align__(16) __half h_xin [(size_t)NTOK*512];
__device__ __align__(16) __half h_ao  [(size_t)NTOK*512];
__device__ __align__(16) __half h_lg  [(size_t)NTOK*128];
__device__ __align__(16) __half h_x2  [(size_t)NTOK*512];
__device__ __align__(16) __half h_ffh [(size_t)NTOK*2048];
__device__ __align__(16) __half h_hin [(size_t)NTOK*896];
__device__ __align__(16) __half h_lgin[(size_t)NTOK*768];
__device__ __align__(16) __half h_w1  [1536*512];
__device__ __align__(16) __half h_w2  [512*512];
__device__ __align__(16) __half h_uw  [512*128];
__device__ __align__(16) __half h_w3  [2048*512];
__device__ __align__(16) __half h_w4  [512*2048];
__device__ __align__(16) __half h_hw  [256*896];
__device__ __align__(16) __half h_vw  [128*768];

__device__ __forceinline__ float nonsat_f(float x) {
    float y = x;
#pragma unroll 1
    for (int it = 0; it < 32; ++it) {
        float y2 = y * y;
        float yn = __fdividef(0.66666668f * y * y2 + x, y2 + 1.0f);
        float d = fabsf(yn - y);
        y = yn;
        if (d <= 1e-6f) break;
    }
    return y;
}

__device__ __forceinline__ uint32_t su32(const void* p) {
    uint32_t a;
    asm("{ .reg .u64 t; cvta.to.shared.u64 t, %1; cvt.u32.u64 %0, t; }" : "=r"(a) : "l"(p));
    return a;
}
__device__ __forceinline__ void cp16(uint32_t s, const void* g) {
    asm volatile("cp.async.cg.shared.global [%0], [%1], 16;"
                 :: "r"(s), "l"(__cvta_generic_to_global(g)) : "memory");
}
__device__ __forceinline__ void cp_commit() {
    asm volatile("cp.async.commit_group;" ::: "memory");
}
template<int N> __device__ __forceinline__ void cp_wait() {
    asm volatile("cp.async.wait_group %0;" :: "n"(N) : "memory");
}
__device__ __forceinline__ void ldmx4(uint32_t* r, uint32_t addr) {
    asm volatile("ldmatrix.sync.aligned.m8n8.x4.shared.b16 {%0,%1,%2,%3}, [%4];"
        : "=r"(r[0]), "=r"(r[1]), "=r"(r[2]), "=r"(r[3]) : "r"(addr));
}
__device__ __forceinline__ void ldmx4t(uint32_t* r, uint32_t addr) {
    asm volatile("ldmatrix.sync.aligned.m8n8.x4.trans.shared.b16 {%0,%1,%2,%3}, [%4];"
        : "=r"(r[0]), "=r"(r[1]), "=r"(r[2]), "=r"(r[3]) : "r"(addr));
}
__device__ __forceinline__ void mma16816(float* c, const uint32_t* a, const uint32_t* b) {
    asm volatile(
        "mma.sync.aligned.m16n8k16.row.col.f32.f16.f16.f32 "
        "{%0,%1,%2,%3}, {%4,%5,%6,%7}, {%8,%9}, {%0,%1,%2,%3};\n"
        : "+f"(c[0]), "+f"(c[1]), "+f"(c[2]), "+f"(c[3])
        : "r"(a[0]), "r"(a[1]), "r"(a[2]), "r"(a[3]), "r"(b[0]), "r"(b[1]));
}
__device__ __forceinline__ uint32_t pkh2(float lo, float hi) {
    __half2 h = __floats2half2_rn(lo, hi);
    return *(uint32_t*)&h;
}
__device__ __forceinline__ void store_h2(__half* H, size_t idx, float a, float b) {
    *(__half2*)(H + idx) = __floats2half2_rn(a, b);
}

// ---------------- merged fp32->fp16 convert (weights + x_in, 1 launch) ----------------
#define SEG0 196608
#define SEG1 262144
#define SEG2 278528
#define SEG3 540672
#define SEG4 802816
#define SEG5 827392
#define SEGT 1875968

__global__ void __launch_bounds__(256) cvt_all_kernel(
    const float* __restrict__ s0, const float* __restrict__ s1,
    const float* __restrict__ s2, const float* __restrict__ s3,
    const float* __restrict__ s4, const float* __restrict__ s5,
    const float* __restrict__ s6)
{
    int i = blockIdx.x * 256 + threadIdx.x;
    if (i >= SEGT) return;
    const float* src; __half* dst; int rel;
    if (i < SEG0)      { src = s0; dst = h_w1; rel = i; }
    else if (i < SEG1) { src = s1; dst = h_w2; rel = i - SEG0; }
    else if (i < SEG2) { src = s2; dst = h_uw; rel = i - SEG1; }
    else if (i < SEG3) { src = s3; dst = h_w3; rel = i - SEG2; }
    else if (i < SEG4) { src = s4; dst = h_w4; rel = i - SEG3; }
    else if (i < SEG5) { src = s5; dst = h_vw; rel = i - SEG4; }
    else               { src = s6; dst = h_xin; rel = i - SEG5; }
    float4 v = ((const float4*)src)[rel];
    ((__half2*)dst)[2*rel]   = __floats2half2_rn(v.x, v.y);
    ((__half2*)dst)[2*rel+1] = __floats2half2_rn(v.z, v.w);
}

// pack hidden-GEMM input: row u = [x1(perm) | hidden_prev | stack_top | 0pad], K=896
__global__ void __launch_bounds__(256) pack_hidden_in(
    const float* __restrict__ x1, const float* __restrict__ hp,
    const float* __restrict__ sp, __half* __restrict__ H)
{
    int idx = blockIdx.x * 256 + threadIdx.x;
    if (idx >= NTOK * 448) return;
    int u = idx / 448, col = (idx % 448) << 1;
    float a = 0.f, b = 0.f;
    if (col < 512) {
        int tp = ((u & 1023) << 3) | (u >> 10);
        float2 v = *(const float2*)(x1 + (size_t)tp * 512 + col);
        a = v.x; b = v.y;
    } else if (col < 768) {
        float2 v = *(const float2*)(hp + (size_t)u * 256 + col - 512);
        a = v.x; b = v.y;
    } else if (col < 864) {
        float2 v = *(const float2*)(sp + (size_t)u * 4608 + col - 768);
        a = v.x; b = v.y;
    }
    store_h2(H, (size_t)u * 896 + col, a, b);
}

__global__ void __launch_bounds__(256) pack_hw(
    const float* __restrict__ Ww, const float* __restrict__ Rw, const float* __restrict__ Pw,
    const float* __restrict__ Wb, const float* __restrict__ Rb, const float* __restrict__ Pb,
    __half* __restrict__ H, float* __restrict__ bsum)
{
    int idx = blockIdx.x * 256 + threadIdx.x;
    if (idx < 256) bsum[idx] = Wb[idx] + Rb[idx] + Pb[idx];
    if (idx >= 256 * 448) return;
    int n = idx / 448, col = (idx % 448) << 1;
    float a = 0.f, b = 0.f;
    if (col < 512) {
        float2 v = *(const float2*)(Ww + (size_t)n * 512 + col);
        a = v.x; b = v.y;
    } else if (col < 768) {
        float2 v = *(const float2*)(Rw + (size_t)n * 256 + col - 512);
        a = v.x; b = v.y;
    } else if (col < 864) {
        float2 v = *(const float2*)(Pw + (size_t)n * 96 + col - 768);
        a = v.x; b = v.y;
    }
    store_h2(H, (size_t)n * 896 + col, a, b);
}

__global__ void __launch_bounds__(256) pack_logits_in(
    const float* __restrict__ x1, const float* __restrict__ hid, __half* __restrict__ H)
{
    int idx = blockIdx.x * 256 + threadIdx.x;
    if (idx >= NTOK * 384) return;
    int t = idx / 384, col = (idx % 384) << 1;
    float a, b;
    if (col < 512) {
        float2 v = *(const float2*)(x1 + (size_t)t * 512 + col);
        a = v.x; b = v.y;
    } else {
        int up = ((t & 7) << 10) | (t >> 3);
        float2 v = *(const float2*)(hid + (size_t)up * 256 + col - 512);
        a = v.x; b = v.y;
    }
    store_h2(H, (size_t)t * 768 + col, a, b);
}

// ---------------- fp16 HMMA GEMM: 8 warps, warp tile 64x32, cp.async 2-stage ----------------
// stage: A 0 (16KB), B 16384 (16KB); stage 32KB, total 64KB
#define T_A 0
#define T_B 16384
#define T_STAGE 32768
#define T_SMEM  65536

template<int EPI, int OUT>
__global__ void __launch_bounds__(256) tgemm(
    const __half* __restrict__ A, const __half* __restrict__ W,
    const float* __restrict__ bias, const float* __restrict__ res,
    float* __restrict__ C, __half* __restrict__ Ch,
    int M, int N, int K)
{
    extern __shared__ char smem[];
    const uint32_t sbase = su32(smem);
    const int tid = threadIdx.x, wid = tid >> 5, lane = tid & 31;
    const int m0 = blockIdx.y * 128, n0 = blockIdx.x * 128;
    const int g = lane >> 2, t2 = (lane & 3) << 1;
    const int wr = (wid & 1) << 6;
    const int wc = (wid >> 1) << 5;
    const int l7 = lane & 7, lr15 = lane & 15;
    const uint32_t swz = (uint32_t)(l7 << 4);
    const int aklo = (lane >> 4) << 3;
    const int bklo = ((lane >> 3) & 1) << 3;
    const uint32_t arow = (uint32_t)((wr + lr15) << 7);
    const uint32_t brow = (uint32_t)((wc + l7 + ((lane >> 4) << 3)) << 7);

    uint32_t soff[4]; size_t gaoff[4], gboff[4];
#pragma unroll
    for (int t = 0; t < 4; t++) {
        int e = tid + (t << 8);
        int r = e >> 3, q = e & 7;
        uint32_t off = (uint32_t)((r << 7) + (q << 4));
        off ^= (off >> 3) & 0x70;
        soff[t] = off;
        gaoff[t] = (size_t)(m0 + r) * K + (q << 3);
        gboff[t] = (size_t)(n0 + r) * K + (q << 3);
    }

    float c[4][4][4];
#pragma unroll
    for (int i = 0; i < 4; i++)
#pragma unroll
        for (int j = 0; j < 4; j++)
#pragma unroll
            for (int q = 0; q < 4; q++) c[i][j][q] = 0.f;

    const int nch = K >> 6;

#define ISSUE_CHUNK(CH, BUF) do { \
    const int k0_ = (CH) << 6; \
    const uint32_t sb_ = sbase + (BUF) * T_STAGE; \
    for (int t_ = 0; t_ < 4; t_++) { \
        cp16(sb_ + T_A + soff[t_], A + gaoff[t_] + k0_); \
        cp16(sb_ + T_B + soff[t_], W + gboff[t_] + k0_); \
    } \
    cp_commit(); \
} while (0)

    ISSUE_CHUNK(0, 0);
    for (int ch = 0; ch < nch; ch++) {
        if (ch + 1 < nch) { ISSUE_CHUNK(ch + 1, (ch + 1) & 1); cp_wait<1>(); }
        else cp_wait<0>();
        __syncthreads();
        const uint32_t bb = sbase + (ch & 1) * T_STAGE;
#pragma unroll
        for (int kk = 0; kk < 64; kk += 16) {
            uint32_t bf[2][4];
            const uint32_t boff = ((uint32_t)((kk + bklo) << 1)) ^ swz;
#pragma unroll
            for (int bi = 0; bi < 2; bi++)
                ldmx4(bf[bi], bb + T_B + brow + (uint32_t)(bi << 11) + boff);
            const uint32_t aoff = ((uint32_t)((kk + aklo) << 1)) ^ swz;
#pragma unroll
            for (int mi = 0; mi < 4; mi++) {
                uint32_t af[4];
                ldmx4(af, bb + T_A + arow + (uint32_t)(mi << 11) + aoff);
#pragma unroll
                for (int bi = 0; bi < 2; bi++) {
                    mma16816(c[mi][2*bi],   af, &bf[bi][0]);
                    mma16816(c[mi][2*bi+1], af, &bf[bi][2]);
                }
            }
        }
        __syncthreads();
    }
#undef ISSUE_CHUNK

#pragma unroll
    for (int mi = 0; mi < 4; mi++) {
#pragma unroll
        for (int ni = 0; ni < 4; ni++) {
            int row = m0 + wr + (mi << 4) + g;
            int col = n0 + wc + (ni << 3) + t2;
#pragma unroll
            for (int h = 0; h < 2; h++) {
                int rr = row + h * 8;
                float v0 = c[mi][ni][2 * h], v1 = c[mi][ni][2 * h + 1];
                if (EPI == 0) {
                    v0 += bias[col]; v1 += bias[col + 1];
                } else if (EPI == 1) {
                    v0 = nonsat_f(v0 + bias[col]); v1 = nonsat_f(v1 + bias[col + 1]);
                } else if (EPI == 2) {
                    const float2 rv = *(const float2*)(res + (size_t)rr * N + col);
                    v0 = 0.5f * (v0 + rv.x); v1 = 0.5f * (v1 + rv.y);
                }
                if (OUT == 0 || OUT == 2) {
                    float2 o; o.x = v0; o.y = v1;
                    *(float2*)(C + (size_t)rr * N + col) = o;
                }
                if (OUT == 1 || OUT == 2) {
                    store_h2(Ch, (size_t)rr * N + col, v0, v1);
                }
            }
        }
    }
}

// ---------------- fp16 HMMA flash attention: 128 q-rows/CTA, cp.async 2-stage ----------------
// smem: Q 0 (16KB); stage s at 16384 + s*16384 {K+0 (8KB), V+8192 (8KB)}
#define A_SMEM 49152

__global__ void __launch_bounds__(256) attn_kernel(
    const __half* __restrict__ Q, __half* __restrict__ ao)
{
    extern __shared__ char sm[];
    const int qt = blockIdx.x, q0 = qt << 7;
    const int b = blockIdx.y >> 3, h = blockIdx.y & 7;
    const int tid = threadIdx.x, wid = tid >> 5, lane = tid & 31;
    const int g = lane >> 2, t2 = (lane & 3) << 1;
    const uint32_t sbase = su32(sm);
    const int l7 = lane & 7, lr15 = lane & 15;
    const uint32_t swz = (uint32_t)(l7 << 4);
    const int klo8 = (lane >> 4) << 3;
    const int bk8 = ((lane >> 3) & 1) << 3;
    const int wq = wid << 4;

    uint32_t qoff[4]; int qrow[4], qq8[4];
#pragma unroll
    for (int t = 0; t < 4; t++) {
        int e = tid + (t << 8);
        int r = e >> 3, q = e & 7;
        uint32_t off = (uint32_t)((r << 7) + (q << 4));
        off ^= (off >> 3) & 0x70;
        qoff[t] = off; qrow[t] = r; qq8[t] = q << 3;
    }

    const size_t qbase = ((size_t)q0 * TB + b) * 1536 + h * 64;
#pragma unroll
    for (int t = 0; t < 4; t++) {
        const size_t gs = qbase + (size_t)qrow[t] * (TB * 1536) + qq8[t];
        cp16(sbase + qoff[t], Q + gs);
    }
#define ISSUE_KV(KT, BUF) do { \
    const size_t kb_ = ((size_t)((KT) << 6) * TB + b) * 1536 + h * 64; \
    const uint32_t st_ = sbase + 16384 + (BUF) * 16384; \
    for (int t_ = 0; t_ < 2; t_++) { \
        const size_t gk_ = kb_ + (size_t)qrow[t_] * (TB * 1536) + 512 + qq8[t_]; \
        const size_t gv_ = kb_ + (size_t)qrow[t_] * (TB * 1536) + 1024 + qq8[t_]; \
        cp16(st_ + 0    + qoff[t_], Q + gk_); \
        cp16(st_ + 8192 + qoff[t_], Q + gv_); \
    } \
    cp_commit(); \
} while (0)
    ISSUE_KV(0, 0);

    float o[8][4];
#pragma unroll
    for (int i = 0; i < 8; i++)
#pragma unroll
        for (int j = 0; j < 4; j++) o[i][j] = 0.f;
    float m0 = -1e30f, m1 = -1e30f, l0 = 0.f, l1 = 0.f;

    const uint32_t aA = sbase + (uint32_t)((wq + lr15) << 7);
    const uint32_t brel = (uint32_t)((l7 + ((lane >> 4) << 3)) << 7);
    const uint32_t vrel = (uint32_t)((l7 + (((lane >> 3) & 1) << 3)) << 7);

    const int ntiles = (qt << 1) + 2;
    for (int kt = 0; kt < ntiles; kt++) {
        const int kv0 = kt << 6;
        if (kt + 1 < ntiles) { ISSUE_KV(kt + 1, (kt + 1) & 1); cp_wait<1>(); }
        else cp_wait<0>();
        __syncthreads();
        const uint32_t st = sbase + 16384 + (kt & 1) * 16384;

        float sc[8][4];
#pragma unroll
        for (int i = 0; i < 8; i++)
#pragma unroll
            for (int j = 0; j < 4; j++) sc[i][j] = 0.f;
#pragma unroll
        for (int kk = 0; kk < 64; kk += 16) {
            uint32_t qf[4];
            const uint32_t aoff = ((uint32_t)((kk + klo8) << 1)) ^ swz;
            ldmx4(qf, aA + aoff);
            const uint32_t boff = ((uint32_t)((kk + bk8) << 1)) ^ swz;
#pragma unroll
            for (int bi = 0; bi < 4; bi++) {
                uint32_t kf[4];
                ldmx4(kf, st + brel + (uint32_t)(bi << 11) + boff);
                mma16816(sc[2*bi],   qf, &kf[0]);
                mma16816(sc[2*bi+1], qf, &kf[2]);
            }
        }

        const int r0 = q0 + wq + g, r1 = r0 + 8;
        const bool diag = (kv0 + 63 > r0);
        float tm0 = -1e30f, tm1 = -1e30f;
#pragma unroll
        for (int ni = 0; ni < 8; ni++) {
            const int cb = kv0 + (ni << 3) + t2;
            float s0 = sc[ni][0] * 0.125f, s1 = sc[ni][1] * 0.125f;
            float s2 = sc[ni][2] * 0.125f, s3 = sc[ni][3] * 0.125f;
            if (diag) {
                if (cb     > r0) s0 = -1e30f;
                if (cb + 1 > r0) s1 = -1e30f;
                if (cb     > r1) s2 = -1e30f;
                if (cb + 1 > r1) s3 = -1e30f;
            }
            sc[ni][0] = s0; sc[ni][1] = s1; sc[ni][2] = s2; sc[ni][3] = s3;
            tm0 = fmaxf(tm0, fmaxf(s0, s1));
            tm1 = fmaxf(tm1, fmaxf(s2, s3));
        }
        tm0 = fmaxf(tm0, __shfl_xor_sync(0xffffffffu, tm0, 1));
        tm0 = fmaxf(tm0, __shfl_xor_sync(0xffffffffu, tm0, 2));
        tm1 = fmaxf(tm1, __shfl_xor_sync(0xffffffffu, tm1, 1));
        tm1 = fmaxf(tm1, __shfl_xor_sync(0xffffffffu, tm1, 2));
        const float mn0 = fmaxf(m0, tm0), mn1 = fmaxf(m1, tm1);
        const float al0 = __expf(m0 - mn0), al1 = __expf(m1 - mn1);
        m0 = mn0; m1 = mn1;
        float ps0 = 0.f, ps1 = 0.f;
#pragma unroll
        for (int ni = 0; ni < 8; ni++) {
            float p0 = __expf(sc[ni][0] - m0), p1 = __expf(sc[ni][1] - m0);
            float p2 = __expf(sc[ni][2] - m1), p3 = __expf(sc[ni][3] - m1);
            sc[ni][0] = p0; sc[ni][1] = p1; sc[ni][2] = p2; sc[ni][3] = p3;
            ps0 += p0 + p1; ps1 += p2 + p3;
        }
        ps0 += __shfl_xor_sync(0xffffffffu, ps0, 1);
        ps0 += __shfl_xor_sync(0xffffffffu, ps0, 2);
        ps1 += __shfl_xor_sync(0xffffffffu, ps1, 1);
        ps1 += __shfl_xor_sync(0xffffffffu, ps1, 2);
        l0 = l0 * al0 + ps0;
        l1 = l1 * al1 + ps1;
#pragma unroll
        for (int ni = 0; ni < 8; ni++) {
            o[ni][0] *= al0; o[ni][1] *= al0;
            o[ni][2] *= al1; o[ni][3] *= al1;
        }

#pragma unroll
        for (int j = 0; j < 4; j++) {
            uint32_t pa[4];
            pa[0] = pkh2(sc[2*j][0],   sc[2*j][1]);
            pa[1] = pkh2(sc[2*j][2],   sc[2*j][3]);
            pa[2] = pkh2(sc[2*j+1][0], sc[2*j+1][1]);
            pa[3] = pkh2(sc[2*j+1][2], sc[2*j+1][3]);
#pragma unroll
            for (int i = 0; i < 4; i++) {
                uint32_t vf[4];
                const uint32_t voff = (uint32_t)(j << 11) +
                    (((uint32_t)(((i << 4) + klo8) << 1)) ^ swz);
                ldmx4t(vf, st + 8192 + vrel + voff);
                mma16816(o[2*i],   pa, &vf[0]);
                mma16816(o[2*i+1], pa, &vf[2]);
            }
        }
        __syncthreads();
    }
#undef ISSUE_KV

    const float inv0 = __fdividef(1.f, l0), inv1 = __fdividef(1.f, l1);
    const int qg0 = q0 + wq + g;
    const size_t dst0 = ((size_t)qg0 * TB + b) * 512 + h * 64 + t2;
    const size_t dst1 = dst0 + (size_t)8 * TB * 512;
#pragma unroll
    for (int ni = 0; ni < 8; ni++) {
        const int d = ni << 3;
        store_h2(ao, dst0 + d, o[ni][0] * inv0, o[ni][1] * inv0);
        store_h2(ao, dst1 + d, o[ni][2] * inv1, o[ni][3] * inv1);
    }
}

template<bool NS>
__global__ void __launch_bounds__(256) add_ln_kernel(
    const float* __restrict__ xa, const float* __restrict__ xb,
    const float* __restrict__ g, const float* __restrict__ bl,
    float* __restrict__ out)
{
    const int t = blockIdx.x, tid = threadIdx.x;
    __shared__ float red[8];
    const size_t base = (size_t)t * TE;
    float v0 = xa[base+tid] + xb[base+tid];
    float v1 = xa[base+tid+256] + xb[base+tid+256];
    float s = v0 + v1;
#pragma unroll
    for (int o = 16; o; o >>= 1) s += __shfl_xor_sync(0xffffffffu, s, o);
    if ((tid & 31) == 0) red[tid>>5] = s;
    __syncthreads();
    if (tid == 0) { float tt=0; for (int w=0;w<8;w++) tt+=red[w]; red[0]=tt; }
    __syncthreads();
    const float mean = red[0] * (1.0f/512.0f);
    __syncthreads();
    float d0 = v0-mean, d1 = v1-mean;
    float q = d0*d0 + d1*d1;
#pragma unroll
    for (int o = 16; o; o >>= 1) q += __shfl_xor_sync(0xffffffffu, q, o);
    if ((tid & 31) == 0) red[tid>>5] = q;
    __syncthreads();
    if (tid == 0) { float tt=0; for (int w=0;w<8;w++) tt+=red[w]; red[0]=tt; }
    __syncthreads();
    const float rs = rsqrtf(red[0]*(1.0f/512.0f) + 1e-5f);
    float o0 = d0*rs*g[tid]     + bl[tid];
    float o1 = d1*rs*g[tid+256] + bl[tid+256];
    if (NS) { o0 = nonsat_f(o0); o1 = nonsat_f(o1); }
    out[base+tid] = o0;
    out[base+tid+256] = o1;
}

__global__ void __launch_bounds__(256) softmax128_kernel(
    const float* __restrict__ lg, __half* __restrict__ H)
{
    const int t = blockIdx.x * 8 + (threadIdx.x >> 5);
    const int lane = threadIdx.x & 31;
    float4 v = *((const float4*)(lg + (size_t)t * 128) + lane);
    float mx = fmaxf(fmaxf(v.x, v.y), fmaxf(v.z, v.w));
#pragma unroll
    for (int o = 16; o; o >>= 1) mx = fmaxf(mx, __shfl_xor_sync(0xffffffffu, mx, o));
    v.x = __expf(v.x-mx); v.y = __expf(v.y-mx); v.z = __expf(v.z-mx); v.w = __expf(v.w-mx);
    float s = v.x + v.y + v.z + v.w;
#pragma unroll
    for (int o = 16; o; o >>= 1) s += __shfl_xor_sync(0xffffffffu, s, o);
    float is = __fdividef(1.f, s);
    const size_t base = (size_t)t * 128 + (lane << 2);
    store_h2(H, base,     v.x * is, v.y * is);
    store_h2(H, base + 2, v.z * is, v.w * is);
}

__global__ void __launch_bounds__(128) stack_kernel(
    const float* __restrict__ hidden, const float* __restrict__ sp,
    const float* __restrict__ Aw, const float* __restrict__ Ab,
    const float* __restrict__ Dw, const float* __restrict__ Db,
    float* __restrict__ out)
{
    __shared__ __align__(16) float h[256];
    __shared__ __align__(16) float inp[96];
    __shared__ float ctl[3];
    const int u = blockIdx.x, tid = threadIdx.x;
    const float* hrow = hidden + (size_t)u * 256;
    h[tid] = hrow[tid]; h[tid+128] = hrow[tid+128];
    __syncthreads();
    if (tid < 96) {
        const float* w = Dw + tid * 256;
        float s = Db[tid];
        for (int k = 0; k < 256; k += 4) {
            float4 wv = *(const float4*)(w + k);
            s += wv.x*h[k] + wv.y*h[k+1] + wv.z*h[k+2] + wv.w*h[k+3];
        }
        inp[tid] = nonsat_f(s);
    } else if (tid < 99) {
        int i = tid - 96;
        const float* w = Aw + i * 256;
        float s = Ab[i];
        for (int k = 0; k < 256; k++) s += w[k]*h[k];
        ctl[i] = s;
    }
    __syncthreads();
    float mx = fmaxf(ctl[0], fmaxf(ctl[1], ctl[2]));
    float e0 = __expf(ctl[0]-mx), e1 = __expf(ctl[1]-mx), e2 = __expf(ctl[2]-mx);
    float is = __fdividef(1.f, e0+e1+e2);
    float c0 = e0*is, c1 = e1*is, c2 = e2*is;
    const float4* prev = (const float4*)(sp + (size_t)u * 4608);
    float4* dst = (float4*)(out + (size_t)u * 4608);
    const float4* inp4 = (const float4*)inp;
    for (int idx = tid; idx < 1152; idx += 128) {
        int d = idx / 24;
        float4 p = prev[idx];
        float4 up = (d == 0) ? inp4[idx] : prev[idx-24];
        float4 dn;
        if (d == 47) { dn.x=dn.y=dn.z=dn.w=0.f; } else dn = prev[idx+24];
        float4 o;
        o.x = c2*p.x + c0*up.x + c1*dn.x;
        o.y = c2*p.y + c0*up.y + c1*dn.y;
        o.z = c2*p.z + c0*up.z + c1*dn.z;
        o.w = c2*p.w + c0*up.w + c1*dn.w;
        dst[idx] = o;
    }
}

extern "C" void kernel_launch(void* const* d_in, const int* in_sizes, int n_in,
                              void* d_out, int out_size) {
    const float* x_in = (const float*)d_in[0];
    const float* hidden_prev = (const float*)d_in[1];
    const float* stack_prev  = (const float*)d_in[2];
    const float* in_proj_w = (const float*)d_in[3];
    const float* in_proj_b = (const float*)d_in[4];
    const float* out_proj_w = (const float*)d_in[5];
    const float* out_proj_b = (const float*)d_in[6];
    const float* ln1_g = (const float*)d_in[7];
    const float* ln1_b = (const float*)d_in[8];
    const float* ln2_g = (const float*)d_in[9];
    const float* ln2_b = (const float*)d_in[10];
    const float* W_w = (const float*)d_in[11];
    const float* W_b = (const float*)d_in[12];
    const float* R_w = (const float*)d_in[13];
    const float* R_b = (const float*)d_in[14];
    const float* P_w = (const float*)d_in[15];
    const float* P_b = (const float*)d_in[16];
    const float* V_w = (const float*)d_in[17];
    const float* U_w = (const float*)d_in[18];
    const float* A_w = (const float*)d_in[19];
    const float* A_b = (const float*)d_in[20];
    const float* D_w = (const float*)d_in[21];
    const float* D_b = (const float*)d_in[22];
    const float* ffi_w = (const float*)d_in[23];
    const float* ffi_b = (const float*)d_in[24];
    const float* ffo_w = (const float*)d_in[25];
    const float* ffo_b = (const float*)d_in[26];

    static bool init_done = false;
    static float *p_proj,*p_x1,*p_lg,*p_x2,*p_ffo,*p_hb;
    static __half *ph_qkv,*ph_xin,*ph_ao,*ph_lg,*ph_x2,*ph_ffh,*ph_hin,*ph_lgin;
    static __half *ph_w1,*ph_w2,*ph_uw,*ph_w3,*ph_w4,*ph_hw,*ph_vw;
    if (!init_done) {
        cudaGetSymbolAddress((void**)&p_proj, g_proj);
        cudaGetSymbolAddress((void**)&p_x1,   g_x1);
        cudaGetSymbolAddress((void**)&p_lg,   g_lg);
        cudaGetSymbolAddress((void**)&p_x2,   g_x2);
        cudaGetSymbolAddress((void**)&p_ffo,  g_ffo);
        cudaGetSymbolAddress((void**)&p_hb,   g_hb);
        cudaGetSymbolAddress((void**)&ph_qkv,  h_qkv);
        cudaGetSymbolAddress((void**)&ph_xin,  h_xin);
        cudaGetSymbolAddress((void**)&ph_ao,   h_ao);
        cudaGetSymbolAddress((void**)&ph_lg,   h_lg);
        cudaGetSymbolAddress((void**)&ph_x2,   h_x2);
        cudaGetSymbolAddress((void**)&ph_ffh,  h_ffh);
        cudaGetSymbolAddress((void**)&ph_hin,  h_hin);
        cudaGetSymbolAddress((void**)&ph_lgin, h_lgin);
        cudaGetSymbolAddress((void**)&ph_w1,   h_w1);
        cudaGetSymbolAddress((void**)&ph_w2,   h_w2);
        cudaGetSymbolAddress((void**)&ph_uw,   h_uw);
        cudaGetSymbolAddress((void**)&ph_w3,   h_w3);
        cudaGetSymbolAddress((void**)&ph_w4,   h_w4);
        cudaGetSymbolAddress((void**)&ph_hw,   h_hw);
        cudaGetSymbolAddress((void**)&ph_vw,   h_vw);
        cudaFuncSetAttribute(tgemm<0,0>, cudaFuncAttributeMaxDynamicSharedMemorySize, T_SMEM);
        cudaFuncSetAttribute(tgemm<0,1>, cudaFuncAttributeMaxDynamicSharedMemorySize, T_SMEM);
        cudaFuncSetAttribute(tgemm<1,0>, cudaFuncAttributeMaxDynamicSharedMemorySize, T_SMEM);
        cudaFuncSetAttribute(tgemm<1,1>, cudaFuncAttributeMaxDynamicSharedMemorySize, T_SMEM);
        cudaFuncSetAttribute(tgemm<2,2>, cudaFuncAttributeMaxDynamicSharedMemorySize, T_SMEM);
        cudaFuncSetAttribute(tgemm<3,0>, cudaFuncAttributeMaxDynamicSharedMemorySize, T_SMEM);
        cudaFuncSetAttribute(attn_kernel, cudaFuncAttributeMaxDynamicSharedMemorySize, A_SMEM);
        init_done = true;
    }

    float* out_x = (float*)d_out;
    float* out_hidden = out_x + (size_t)NTOK * TE;
    float* out_stack  = out_hidden + (size_t)NTOK * TDH;

    // single batched convert (6 weights + x_in) + hidden weight pack
    cvt_all_kernel<<<(SEGT + 255)/256, 256>>>(in_proj_w, out_proj_w, U_w,
                                              ffi_w, ffo_w, V_w, x_in);
    pack_hw<<<(256*448 + 255)/256, 256>>>(W_w, R_w, P_w, W_b, R_b, P_b, ph_hw, p_hb);

    // 1) qkv (fp16 out)
    tgemm<0,1><<<dim3(12,64),256,T_SMEM>>>(ph_xin, ph_w1,
        in_proj_b, nullptr, nullptr, ph_qkv, NTOK, 1536, 512);
    // 2) flash attention (128 q-rows per CTA)
    attn_kernel<<<dim3(8,64),256,A_SMEM>>>(ph_qkv, ph_ao);
    // 3) out projection
    tgemm<0,0><<<dim3(4,64),256,T_SMEM>>>(ph_ao, ph_w2,
        out_proj_b, nullptr, p_proj, nullptr, NTOK, 512, 512);
    // 4) x1 = nonsat(LN(x_in + proj))
    add_ln_kernel<true><<<NTOK,256>>>(x_in, p_proj, ln1_g, ln1_b, p_x1);
    // 5) hidden via HMMA
    pack_hidden_in<<<(NTOK*448 + 255)/256, 256>>>(p_x1, hidden_prev, stack_prev, ph_hin);
    tgemm<1,0><<<dim3(2,64),256,T_SMEM>>>(ph_hin, ph_hw,
        p_hb, nullptr, out_hidden, nullptr, NTOK, 256, 896);
    // 6) logits via HMMA
    pack_logits_in<<<(NTOK*384 + 255)/256, 256>>>(p_x1, out_hidden, ph_lgin);
    tgemm<3,0><<<dim3(1,64),256,T_SMEM>>>(ph_lgin, ph_vw,
        nullptr, nullptr, p_lg, nullptr, NTOK, 128, 768);
    // 7) softmax (fp16 out)
    softmax128_kernel<<<NTOK/8,256>>>(p_lg, ph_lg);
    // 8) x2 = 0.5*(x1 + sm @ U_w.T)   (fp32 + fp16 out)
    tgemm<2,2><<<dim3(4,64),256,T_SMEM>>>(ph_lg, ph_uw,
        nullptr, p_x1, p_x2, ph_x2, NTOK, 512, 128);
    // 9) stack
    stack_kernel<<<NTOK,128>>>(out_hidden, stack_prev, A_w, A_b, D_w, D_b, out_stack);
    // 10) ff hidden (fp16 out)
    tgemm<1,1><<<dim3(16,64),256,T_SMEM>>>(ph_x2, ph_w3,
        ffi_b, nullptr, nullptr, ph_ffh, NTOK, 2048, 512);
    // 11) ff out
    tgemm<0,0><<<dim3(4,64),256,T_SMEM>>>(ph_ffh, ph_w4,
        ffo_b, nullptr, p_ffo, nullptr, NTOK, 512, 2048);
    // 12) x_out
    add_ln_kernel<false><<<NTOK,256>>>(p_x2, p_ffo, ln2_g, ln2_b, out_x);
}

// round 16
// speedup vs baseline: 1.0702x; 1.0067x over previous
#include <cuda_runtime.h>
#include <cuda_fp16.h>
#include <math.h>
#include <stdint.h>

#define TS 1024
#define TB 8
#define TE 512
#define TDH 256
#define NTOK 8192

// ---------------- fp32 scratch ----------------
__device__ __align__(16) float g_proj[(size_t)NTOK*TE];
__device__ __align__(16) float g_x1  [(size_t)NTOK*TE];
__device__ __align__(16) float g_lg  [(size_t)NTOK*128];
__device__ __align__(16) float g_x2  [(size_t)NTOK*TE];
__device__ __align__(16) float g_ffo [(size_t)NTOK*TE];
__device__ __align__(16) float g_hb  [256];

// ---------------- fp16 scratch ----------------
__device__ __align__(16) __half h_qkv [(size_t)NTOK*1536];
__device__ __align__(16) __half h_xin [(size_t)NTOK*512];
__device__ __align__(16) __half h_ao  [(size_t)NTOK*512];
__device__ __align__(16) __half h_lg  [(size_t)NTOK*128];
__device__ __align__(16) __half h_x2  [(size_t)NTOK*512];
__device__ __align__(16) __half h_ffh [(size_t)NTOK*2048];
__device__ __align__(16) __half h_hin [(size_t)NTOK*896];
__device__ __align__(16) __half h_lgin[(size_t)NTOK*768];
__device__ __align__(16) __half h_w1  [1536*512];
__device__ __align__(16) __half h_w2  [512*512];
__device__ __align__(16) __half h_uw  [512*128];
__device__ __align__(16) __half h_w3  [2048*512];
__device__ __align__(16) __half h_w4  [512*2048];
__device__ __align__(16) __half h_hw  [256*896];
__device__ __align__(16) __half h_vw  [128*768];

__device__ __forceinline__ float nonsat_f(float x) {
    float y = x;
#pragma unroll 1
    for (int it = 0; it < 32; ++it) {
        float y2 = y * y;
        float yn = __fdividef(0.66666668f * y * y2 + x, y2 + 1.0f);
        float d = fabsf(yn - y);
        y = yn;
        if (d <= 1e-6f) break;
    }
    return y;
}

__device__ __forceinline__ uint32_t su32(const void* p) {
    uint32_t a;
    asm("{ .reg .u64 t; cvta.to.shared.u64 t, %1; cvt.u32.u64 %0, t; }" : "=r"(a) : "l"(p));
    return a;
}
__device__ __forceinline__ void cp16(uint32_t s, const void* g) {
    asm volatile("cp.async.cg.shared.global [%0], [%1], 16;"
                 :: "r"(s), "l"(__cvta_generic_to_global(g)) : "memory");
}
__device__ __forceinline__ void cp_commit() {
    asm volatile("cp.async.commit_group;" ::: "memory");
}
template<int N> __device__ __forceinline__ void cp_wait() {
    asm volatile("cp.async.wait_group %0;" :: "n"(N) : "memory");
}
__device__ __forceinline__ void ldmx4(uint32_t* r, uint32_t addr) {
    asm volatile("ldmatrix.sync.aligned.m8n8.x4.shared.b16 {%0,%1,%2,%3}, [%4];"
        : "=r"(r[0]), "=r"(r[1]), "=r"(r[2]), "=r"(r[3]) : "r"(addr));
}
__device__ __forceinline__ void ldmx4t(uint32_t* r, uint32_t addr) {
    asm volatile("ldmatrix.sync.aligned.m8n8.x4.trans.shared.b16 {%0,%1,%2,%3}, [%4];"
        : "=r"(r[0]), "=r"(r[1]), "=r"(r[2]), "=r"(r[3]) : "r"(addr));
}
__device__ __forceinline__ void mma16816(float* c, const uint32_t* a, const uint32_t* b) {
    asm volatile(
        "mma.sync.aligned.m16n8k16.row.col.f32.f16.f16.f32 "
        "{%0,%1,%2,%3}, {%4,%5,%6,%7}, {%8,%9}, {%0,%1,%2,%3};\n"
        : "+f"(c[0]), "+f"(c[1]), "+f"(c[2]), "+f"(c[3])
        : "r"(a[0]), "r"(a[1]), "r"(a[2]), "r"(a[3]), "r"(b[0]), "r"(b[1]));
}
__device__ __forceinline__ uint32_t pkh2(float lo, float hi) {
    __half2 h = __floats2half2_rn(lo, hi);
    return *(uint32_t*)&h;
}
__device__ __forceinline__ void store_h2(__half* H, size_t idx, float a, float b) {
    *(__half2*)(H + idx) = __floats2half2_rn(a, b);
}

// ---------------- merged fp32->fp16 convert (weights + x_in, 1 launch) ----------------
#define SEG0 196608
#define SEG1 262144
#define SEG2 278528
#define SEG3 540672
#define SEG4 802816
#define SEG5 827392
#define SEGT 1875968

__global__ void __launch_bounds__(256) cvt_all_kernel(
    const float* __restrict__ s0, const float* __restrict__ s1,
    const float* __restrict__ s2, const float* __restrict__ s3,
    const float* __restrict__ s4, const float* __restrict__ s5,
    const float* __restrict__ s6)
{
    int i = blockIdx.x * 256 + threadIdx.x;
    if (i >= SEGT) return;
    const float* src; __half* dst; int rel;
    if (i < SEG0)      { src = s0; dst = h_w1; rel = i; }
    else if (i < SEG1) { src = s1; dst = h_w2; rel = i - SEG0; }
    else if (i < SEG2) { src = s2; dst = h_uw; rel = i - SEG1; }
    else if (i < SEG3) { src = s3; dst = h_w3; rel = i - SEG2; }
    else if (i < SEG4) { src = s4; dst = h_w4; rel = i - SEG3; }
    else if (i < SEG5) { src = s5; dst = h_vw; rel = i - SEG4; }
    else               { src = s6; dst = h_xin; rel = i - SEG5; }
    float4 v = ((const float4*)src)[rel];
    ((__half2*)dst)[2*rel]   = __floats2half2_rn(v.x, v.y);
    ((__half2*)dst)[2*rel+1] = __floats2half2_rn(v.z, v.w);
}

// pack hidden-GEMM input, non-x1 part: cols [512,896) = [hp | stack_top | 0pad]
__global__ void __launch_bounds__(256) pack_hidden_in(
    const float* __restrict__ hp, const float* __restrict__ sp,
    __half* __restrict__ H)
{
    int idx = blockIdx.x * 256 + threadIdx.x;
    if (idx >= NTOK * 192) return;
    int u = idx / 192, col = 512 + ((idx % 192) << 1);
    float a = 0.f, b = 0.f;
    if (col < 768) {
        float2 v = *(const float2*)(hp + (size_t)u * 256 + col - 512);
        a = v.x; b = v.y;
    } else if (col < 864) {
        float2 v = *(const float2*)(sp + (size_t)u * 4608 + col - 768);
        a = v.x; b = v.y;
    }
    store_h2(H, (size_t)u * 896 + col, a, b);
}

__global__ void __launch_bounds__(256) pack_hw(
    const float* __restrict__ Ww, const float* __restrict__ Rw, const float* __restrict__ Pw,
    const float* __restrict__ Wb, const float* __restrict__ Rb, const float* __restrict__ Pb,
    __half* __restrict__ H, float* __restrict__ bsum)
{
    int idx = blockIdx.x * 256 + threadIdx.x;
    if (idx < 256) bsum[idx] = Wb[idx] + Rb[idx] + Pb[idx];
    if (idx >= 256 * 448) return;
    int n = idx / 448, col = (idx % 448) << 1;
    float a = 0.f, b = 0.f;
    if (col < 512) {
        float2 v = *(const float2*)(Ww + (size_t)n * 512 + col);
        a = v.x; b = v.y;
    } else if (col < 768) {
        float2 v = *(const float2*)(Rw + (size_t)n * 256 + col - 512);
        a = v.x; b = v.y;
    } else if (col < 864) {
        float2 v = *(const float2*)(Pw + (size_t)n * 96 + col - 768);
        a = v.x; b = v.y;
    }
    store_h2(H, (size_t)n * 896 + col, a, b);
}

// pack logits-GEMM input, non-x1 part: cols [512,768) = hidden(perm t)
__global__ void __launch_bounds__(256) pack_logits_in(
    const float* __restrict__ hid, __half* __restrict__ H)
{
    int idx = blockIdx.x * 256 + threadIdx.x;
    if (idx >= NTOK * 128) return;
    int t = idx / 128, col = 512 + ((idx % 128) << 1);
    int up = ((t & 7) << 10) | (t >> 3);
    float2 v = *(const float2*)(hid + (size_t)up * 256 + col - 512);
    store_h2(H, (size_t)t * 768 + col, v.x, v.y);
}

// ---------------- fp16 HMMA GEMM: 8 warps, warp tile 64x32, cp.async 2-stage ----------------
#define T_A 0
#define T_B 16384
#define T_STAGE 32768
#define T_SMEM  65536

template<int EPI, int OUT>
__global__ void __launch_bounds__(256) tgemm(
    const __half* __restrict__ A, const __half* __restrict__ W,
    const float* __restrict__ bias, const float* __restrict__ res,
    float* __restrict__ C, __half* __restrict__ Ch,
    int M, int N, int K)
{
    extern __shared__ char smem[];
    const uint32_t sbase = su32(smem);
    const int tid = threadIdx.x, wid = tid >> 5, lane = tid & 31;
    const int m0 = blockIdx.y * 128, n0 = blockIdx.x * 128;
    const int g = lane >> 2, t2 = (lane & 3) << 1;
    const int wr = (wid & 1) << 6;
    const int wc = (wid >> 1) << 5;
    const int l7 = lane & 7, lr15 = lane & 15;
    const uint32_t swz = (uint32_t)(l7 << 4);
    const int aklo = (lane >> 4) << 3;
    const int bklo = ((lane >> 3) & 1) << 3;
    const uint32_t arow = (uint32_t)((wr + lr15) << 7);
    const uint32_t brow = (uint32_t)((wc + l7 + ((lane >> 4) << 3)) << 7);

    uint32_t soff[4]; size_t gaoff[4], gboff[4];
#pragma unroll
    for (int t = 0; t < 4; t++) {
        int e = tid + (t << 8);
        int r = e >> 3, q = e & 7;
        uint32_t off = (uint32_t)((r << 7) + (q << 4));
        off ^= (off >> 3) & 0x70;
        soff[t] = off;
        gaoff[t] = (size_t)(m0 + r) * K + (q << 3);
        gboff[t] = (size_t)(n0 + r) * K + (q << 3);
    }

    float c[4][4][4];
#pragma unroll
    for (int i = 0; i < 4; i++)
#pragma unroll
        for (int j = 0; j < 4; j++)
#pragma unroll
            for (int q = 0; q < 4; q++) c[i][j][q] = 0.f;

    const int nch = K >> 6;

#define ISSUE_CHUNK(CH, BUF) do { \
    const int k0_ = (CH) << 6; \
    const uint32_t sb_ = sbase + (BUF) * T_STAGE; \
    for (int t_ = 0; t_ < 4; t_++) { \
        cp16(sb_ + T_A + soff[t_], A + gaoff[t_] + k0_); \
        cp16(sb_ + T_B + soff[t_], W + gboff[t_] + k0_); \
    } \
    cp_commit(); \
} while (0)

    ISSUE_CHUNK(0, 0);
    for (int ch = 0; ch < nch; ch++) {
        if (ch + 1 < nch) { ISSUE_CHUNK(ch + 1, (ch + 1) & 1); cp_wait<1>(); }
        else cp_wait<0>();
        __syncthreads();
        const uint32_t bb = sbase + (ch & 1) * T_STAGE;
#pragma unroll
        for (int kk = 0; kk < 64; kk += 16) {
            uint32_t bf[2][4];
            const uint32_t boff = ((uint32_t)((kk + bklo) << 1)) ^ swz;
#pragma unroll
            for (int bi = 0; bi < 2; bi++)
                ldmx4(bf[bi], bb + T_B + brow + (uint32_t)(bi << 11) + boff);
            const uint32_t aoff = ((uint32_t)((kk + aklo) << 1)) ^ swz;
#pragma unroll
            for (int mi = 0; mi < 4; mi++) {
                uint32_t af[4];
                ldmx4(af, bb + T_A + arow + (uint32_t)(mi << 11) + aoff);
#pragma unroll
                for (int bi = 0; bi < 2; bi++) {
                    mma16816(c[mi][2*bi],   af, &bf[bi][0]);
                    mma16816(c[mi][2*bi+1], af, &bf[bi][2]);
                }
            }
        }
        __syncthreads();
    }
#undef ISSUE_CHUNK

#pragma unroll
    for (int mi = 0; mi < 4; mi++) {
#pragma unroll
        for (int ni = 0; ni < 4; ni++) {
            int row = m0 + wr + (mi << 4) + g;
            int col = n0 + wc + (ni << 3) + t2;
#pragma unroll
            for (int h = 0; h < 2; h++) {
                int rr = row + h * 8;
                float v0 = c[mi][ni][2 * h], v1 = c[mi][ni][2 * h + 1];
                if (EPI == 0) {
                    v0 += bias[col]; v1 += bias[col + 1];
                } else if (EPI == 1) {
                    v0 = nonsat_f(v0 + bias[col]); v1 = nonsat_f(v1 + bias[col + 1]);
                } else if (EPI == 2) {
                    const float2 rv = *(const float2*)(res + (size_t)rr * N + col);
                    v0 = 0.5f * (v0 + rv.x); v1 = 0.5f * (v1 + rv.y);
                }
                if (OUT == 0 || OUT == 2) {
                    float2 o; o.x = v0; o.y = v1;
                    *(float2*)(C + (size_t)rr * N + col) = o;
                }
                if (OUT == 1 || OUT == 2) {
                    store_h2(Ch, (size_t)rr * N + col, v0, v1);
                }
            }
        }
    }
}

// ---------------- fp16 HMMA flash attention: 128 q-rows/CTA, cp.async 2-stage ----------------
#define A_SMEM 49152

__global__ void __launch_bounds__(256) attn_kernel(
    const __half* __restrict__ Q, __half* __restrict__ ao)
{
    extern __shared__ char sm[];
    const int qt = blockIdx.x, q0 = qt << 7;
    const int b = blockIdx.y >> 3, h = blockIdx.y & 7;
    const int tid = threadIdx.x, wid = tid >> 5, lane = tid & 31;
    const int g = lane >> 2, t2 = (lane & 3) << 1;
    const uint32_t sbase = su32(sm);
    const int l7 = lane & 7, lr15 = lane & 15;
    const uint32_t swz = (uint32_t)(l7 << 4);
    const int klo8 = (lane >> 4) << 3;
    const int bk8 = ((lane >> 3) & 1) << 3;
    const int wq = wid << 4;

    uint32_t qoff[4]; int qrow[4], qq8[4];
#pragma unroll
    for (int t = 0; t < 4; t++) {
        int e = tid + (t << 8);
        int r = e >> 3, q = e & 7;
        uint32_t off = (uint32_t)((r << 7) + (q << 4));
        off ^= (off >> 3) & 0x70;
        qoff[t] = off; qrow[t] = r; qq8[t] = q << 3;
    }

    const size_t qbase = ((size_t)q0 * TB + b) * 1536 + h * 64;
#pragma unroll
    for (int t = 0; t < 4; t++) {
        const size_t gs = qbase + (size_t)qrow[t] * (TB * 1536) + qq8[t];
        cp16(sbase + qoff[t], Q + gs);
    }
#define ISSUE_KV(KT, BUF) do { \
    const size_t kb_ = ((size_t)((KT) << 6) * TB + b) * 1536 + h * 64; \
    const uint32_t st_ = sbase + 16384 + (BUF) * 16384; \
    for (int t_ = 0; t_ < 2; t_++) { \
        const size_t gk_ = kb_ + (size_t)qrow[t_] * (TB * 1536) + 512 + qq8[t_]; \
        const size_t gv_ = kb_ + (size_t)qrow[t_] * (TB * 1536) + 1024 + qq8[t_]; \
        cp16(st_ + 0    + qoff[t_], Q + gk_); \
        cp16(st_ + 8192 + qoff[t_], Q + gv_); \
    } \
    cp_commit(); \
} while (0)
    ISSUE_KV(0, 0);

    float o[8][4];
#pragma unroll
    for (int i = 0; i < 8; i++)
#pragma unroll
        for (int j = 0; j < 4; j++) o[i][j] = 0.f;
    float m0 = -1e30f, m1 = -1e30f, l0 = 0.f, l1 = 0.f;

    const uint32_t aA = sbase + (uint32_t)((wq + lr15) << 7);
    const uint32_t brel = (uint32_t)((l7 + ((lane >> 4) << 3)) << 7);
    const uint32_t vrel = (uint32_t)((l7 + (((lane >> 3) & 1) << 3)) << 7);

    const int ntiles = (qt << 1) + 2;
    for (int kt = 0; kt < ntiles; kt++) {
        const int kv0 = kt << 6;
        if (kt + 1 < ntiles) { ISSUE_KV(kt + 1, (kt + 1) & 1); cp_wait<1>(); }
        else cp_wait<0>();
        __syncthreads();
        const uint32_t st = sbase + 16384 + (kt & 1) * 16384;

        // per-warp skip of fully-masked tiles (uniform branch: wq is warp-uniform)
        if (kv0 <= q0 + wq + 15) {
            float sc[8][4];
#pragma unroll
            for (int i = 0; i < 8; i++)
#pragma unroll
                for (int j = 0; j < 4; j++) sc[i][j] = 0.f;
#pragma unroll
            for (int kk = 0; kk < 64; kk += 16) {
                uint32_t qf[4];
                const uint32_t aoff = ((uint32_t)((kk + klo8) << 1)) ^ swz;
                ldmx4(qf, aA + aoff);
                const uint32_t boff = ((uint32_t)((kk + bk8) << 1)) ^ swz;
#pragma unroll
                for (int bi = 0; bi < 4; bi++) {
                    uint32_t kf[4];
                    ldmx4(kf, st + brel + (uint32_t)(bi << 11) + boff);
                    mma16816(sc[2*bi],   qf, &kf[0]);
                    mma16816(sc[2*bi+1], qf, &kf[2]);
                }
            }

            const int r0 = q0 + wq + g, r1 = r0 + 8;
            const bool diag = (kv0 + 63 > r0);
            float tm0 = -1e30f, tm1 = -1e30f;
#pragma unroll
            for (int ni = 0; ni < 8; ni++) {
                const int cb = kv0 + (ni << 3) + t2;
                float s0 = sc[ni][0] * 0.125f, s1 = sc[ni][1] * 0.125f;
                float s2 = sc[ni][2] * 0.125f, s3 = sc[ni][3] * 0.125f;
                if (diag) {
                    if (cb     > r0) s0 = -1e30f;
                    if (cb + 1 > r0) s1 = -1e30f;
                    if (cb     > r1) s2 = -1e30f;
                    if (cb + 1 > r1) s3 = -1e30f;
                }
                sc[ni][0] = s0; sc[ni][1] = s1; sc[ni][2] = s2; sc[ni][3] = s3;
                tm0 = fmaxf(tm0, fmaxf(s0, s1));
                tm1 = fmaxf(tm1, fmaxf(s2, s3));
            }
            tm0 = fmaxf(tm0, __shfl_xor_sync(0xffffffffu, tm0, 1));
            tm0 = fmaxf(tm0, __shfl_xor_sync(0xffffffffu, tm0, 2));
            tm1 = fmaxf(tm1, __shfl_xor_sync(0xffffffffu, tm1, 1));
            tm1 = fmaxf(tm1, __shfl_xor_sync(0xffffffffu, tm1, 2));
            const float mn0 = fmaxf(m0, tm0), mn1 = fmaxf(m1, tm1);
            const float al0 = __expf(m0 - mn0), al1 = __expf(m1 - mn1);
            m0 = mn0; m1 = mn1;
            float ps0 = 0.f, ps1 = 0.f;
#pragma unroll
            for (int ni = 0; ni < 8; ni++) {
                float p0 = __expf(sc[ni][0] - m0), p1 = __expf(sc[ni][1] - m0);
                float p2 = __expf(sc[ni][2] - m1), p3 = __expf(sc[ni][3] - m1);
                sc[ni][0] = p0; sc[ni][1] = p1; sc[ni][2] = p2; sc[ni][3] = p3;
                ps0 += p0 + p1; ps1 += p2 + p3;
            }
            ps0 += __shfl_xor_sync(0xffffffffu, ps0, 1);
            ps0 += __shfl_xor_sync(0xffffffffu, ps0, 2);
            ps1 += __shfl_xor_sync(0xffffffffu, ps1, 1);
            ps1 += __shfl_xor_sync(0xffffffffu, ps1, 2);
            l0 = l0 * al0 + ps0;
            l1 = l1 * al1 + ps1;
#pragma unroll
            for (int ni = 0; ni < 8; ni++) {
                o[ni][0] *= al0; o[ni][1] *= al0;
                o[ni][2] *= al1; o[ni][3] *= al1;
            }

#pragma unroll
            for (int j = 0; j < 4; j++) {
                uint32_t pa[4];
                pa[0] = pkh2(sc[2*j][0],   sc[2*j][1]);
                pa[1] = pkh2(sc[2*j][2],   sc[2*j][3]);
                pa[2] = pkh2(sc[2*j+1][0], sc[2*j+1][1]);
                pa[3] = pkh2(sc[2*j+1][2], sc[2*j+1][3]);
#pragma unroll
                for (int i = 0; i < 4; i++) {
                    uint32_t vf[4];
                    const uint32_t voff = (uint32_t)(j << 11) +
                        (((uint32_t)(((i << 4) + klo8) << 1)) ^ swz);
                    ldmx4t(vf, st + 8192 + vrel + voff);
                    mma16816(o[2*i],   pa, &vf[0]);
                    mma16816(o[2*i+1], pa, &vf[2]);
                }
            }
        }
        __syncthreads();
    }
#undef ISSUE_KV

    const float inv0 = __fdividef(1.f, l0), inv1 = __fdividef(1.f, l1);
    const int qg0 = q0 + wq + g;
    const size_t dst0 = ((size_t)qg0 * TB + b) * 512 + h * 64 + t2;
    const size_t dst1 = dst0 + (size_t)8 * TB * 512;
#pragma unroll
    for (int ni = 0; ni < 8; ni++) {
        const int d = ni << 3;
        store_h2(ao, dst0 + d, o[ni][0] * inv0, o[ni][1] * inv0);
        store_h2(ao, dst1 + d, o[ni][2] * inv1, o[ni][3] * inv1);
    }
}

// add+LN; NS variant also scatters fp16 x1 into hidden-pack and logits-pack rows
template<bool NS>
__global__ void __launch_bounds__(256) add_ln_kernel(
    const float* __restrict__ xa, const float* __restrict__ xb,
    const float* __restrict__ g, const float* __restrict__ bl,
    float* __restrict__ out, __half* __restrict__ hin, __half* __restrict__ lgin)
{
    const int t = blockIdx.x, tid = threadIdx.x;
    __shared__ float red[8];
    const size_t base = (size_t)t * TE;
    float v0 = xa[base+tid] + xb[base+tid];
    float v1 = xa[base+tid+256] + xb[base+tid+256];
    float s = v0 + v1;
#pragma unroll
    for (int o = 16; o; o >>= 1) s += __shfl_xor_sync(0xffffffffu, s, o);
    if ((tid & 31) == 0) red[tid>>5] = s;
    __syncthreads();
    if (tid == 0) { float tt=0; for (int w=0;w<8;w++) tt+=red[w]; red[0]=tt; }
    __syncthreads();
    const float mean = red[0] * (1.0f/512.0f);
    __syncthreads();
    float d0 = v0-mean, d1 = v1-mean;
    float q = d0*d0 + d1*d1;
#pragma unroll
    for (int o = 16; o; o >>= 1) q += __shfl_xor_sync(0xffffffffu, q, o);
    if ((tid & 31) == 0) red[tid>>5] = q;
    __syncthreads();
    if (tid == 0) { float tt=0; for (int w=0;w<8;w++) tt+=red[w]; red[0]=tt; }
    __syncthreads();
    const float rs = rsqrtf(red[0]*(1.0f/512.0f) + 1e-5f);
    float o0 = d0*rs*g[tid]     + bl[tid];
    float o1 = d1*rs*g[tid+256] + bl[tid+256];
    if (NS) { o0 = nonsat_f(o0); o1 = nonsat_f(o1); }
    out[base+tid] = o0;
    out[base+tid+256] = o1;
    if (NS) {
        const int u = ((t & 7) << 10) | (t >> 3);   // inverse of tp(u)
        hin[(size_t)u * 896 + tid]        = __float2half(o0);
        hin[(size_t)u * 896 + tid + 256]  = __float2half(o1);
        lgin[(size_t)t * 768 + tid]       = __float2half(o0);
        lgin[(size_t)t * 768 + tid + 256] = __float2half(o1);
    }
}

__global__ void __launch_bounds__(256) softmax128_kernel(
    const float* __restrict__ lg, __half* __restrict__ H)
{
    const int t = blockIdx.x * 8 + (threadIdx.x >> 5);
    const int lane = threadIdx.x & 31;
    float4 v = *((const float4*)(lg + (size_t)t * 128) + lane);
    float mx = fmaxf(fmaxf(v.x, v.y), fmaxf(v.z, v.w));
#pragma unroll
    for (int o = 16; o; o >>= 1) mx = fmaxf(mx, __shfl_xor_sync(0xffffffffu, mx, o));
    v.x = __expf(v.x-mx); v.y = __expf(v.y-mx); v.z = __expf(v.z-mx); v.w = __expf(v.w-mx);
    float s = v.x + v.y + v.z + v.w;
#pragma unroll
    for (int o = 16; o; o >>= 1) s += __shfl_xor_sync(0xffffffffu, s, o);
    float is = __fdividef(1.f, s);
    const size_t base = (size_t)t * 128 + (lane << 2);
    store_h2(H, base,     v.x * is, v.y * is);
    store_h2(H, base + 2, v.z * is, v.w * is);
}

__global__ void __launch_bounds__(128) stack_kernel(
    const float* __restrict__ hidden, const float* __restrict__ sp,
    const float* __restrict__ Aw, const float* __restrict__ Ab,
    const float* __restrict__ Dw, const float* __restrict__ Db,
    float* __restrict__ out)
{
    __shared__ __align__(16) float h[256];
    __shared__ __align__(16) float inp[96];
    __shared__ float ctl[3];
    const int u = blockIdx.x, tid = threadIdx.x;
    const float* hrow = hidden + (size_t)u * 256;
    h[tid] = hrow[tid]; h[tid+128] = hrow[tid+128];
    __syncthreads();
    if (tid < 96) {
        const float* w = Dw + tid * 256;
        float s = Db[tid];
        for (int k = 0; k < 256; k += 4) {
            float4 wv = *(const float4*)(w + k);
            s += wv.x*h[k] + wv.y*h[k+1] + wv.z*h[k+2] + wv.w*h[k+3];
        }
        inp[tid] = nonsat_f(s);
    } else if (tid < 99) {
        int i = tid - 96;
        const float* w = Aw + i * 256;
        float s = Ab[i];
        for (int k = 0; k < 256; k++) s += w[k]*h[k];
        ctl[i] = s;
    }
    __syncthreads();
    float mx = fmaxf(ctl[0], fmaxf(ctl[1], ctl[2]));
    float e0 = __expf(ctl[0]-mx), e1 = __expf(ctl[1]-mx), e2 = __expf(ctl[2]-mx);
    float is = __fdividef(1.f, e0+e1+e2);
    float c0 = e0*is, c1 = e1*is, c2 = e2*is;
    const float4* prev = (const float4*)(sp + (size_t)u * 4608);
    float4* dst = (float4*)(out + (size_t)u * 4608);
    const float4* inp4 = (const float4*)inp;
    for (int idx = tid; idx < 1152; idx += 128) {
        int d = idx / 24;
        float4 p = prev[idx];
        float4 up = (d == 0) ? inp4[idx] : prev[idx-24];
        float4 dn;
        if (d == 47) { dn.x=dn.y=dn.z=dn.w=0.f; } else dn = prev[idx+24];
        float4 o;
        o.x = c2*p.x + c0*up.x + c1*dn.x;
        o.y = c2*p.y + c0*up.y + c1*dn.y;
        o.z = c2*p.z + c0*up.z + c1*dn.z;
        o.w = c2*p.w + c0*up.w + c1*dn.w;
        dst[idx] = o;
    }
}

extern "C" void kernel_launch(void* const* d_in, const int* in_sizes, int n_in,
                              void* d_out, int out_size) {
    const float* x_in = (const float*)d_in[0];
    const float* hidden_prev = (const float*)d_in[1];
    const float* stack_prev  = (const float*)d_in[2];
    const float* in_proj_w = (const float*)d_in[3];
    const float* in_proj_b = (const float*)d_in[4];
    const float* out_proj_w = (const float*)d_in[5];
    const float* out_proj_b = (const float*)d_in[6];
    const float* ln1_g = (const float*)d_in[7];
    const float* ln1_b = (const float*)d_in[8];
    const float* ln2_g = (const float*)d_in[9];
    const float* ln2_b = (const float*)d_in[10];
    const float* W_w = (const float*)d_in[11];
    const float* W_b = (const float*)d_in[12];
    const float* R_w = (const float*)d_in[13];
    const float* R_b = (const float*)d_in[14];
    const float* P_w = (const float*)d_in[15];
    const float* P_b = (const float*)d_in[16];
    const float* V_w = (const float*)d_in[17];
    const float* U_w = (const float*)d_in[18];
    const float* A_w = (const float*)d_in[19];
    const float* A_b = (const float*)d_in[20];
    const float* D_w = (const float*)d_in[21];
    const float* D_b = (const float*)d_in[22];
    const float* ffi_w = (const float*)d_in[23];
    const float* ffi_b = (const float*)d_in[24];
    const float* ffo_w = (const float*)d_in[25];
    const float* ffo_b = (const float*)d_in[26];

    static bool init_done = false;
    static float *p_proj,*p_x1,*p_lg,*p_x2,*p_ffo,*p_hb;
    static __half *ph_qkv,*ph_xin,*ph_ao,*ph_lg,*ph_x2,*ph_ffh,*ph_hin,*ph_lgin;
    static __half *ph_w1,*ph_w2,*ph_uw,*ph_w3,*ph_w4,*ph_hw,*ph_vw;
    if (!init_done) {
        cudaGetSymbolAddress((void**)&p_proj, g_proj);
        cudaGetSymbolAddress((void**)&p_x1,   g_x1);
        cudaGetSymbolAddress((void**)&p_lg,   g_lg);
        cudaGetSymbolAddress((void**)&p_x2,   g_x2);
        cudaGetSymbolAddress((void**)&p_ffo,  g_ffo);
        cudaGetSymbolAddress((void**)&p_hb,   g_hb);
        cudaGetSymbolAddress((void**)&ph_qkv,  h_qkv);
        cudaGetSymbolAddress((void**)&ph_xin,  h_xin);
        cudaGetSymbolAddress((void**)&ph_ao,   h_ao);
        cudaGetSymbolAddress((void**)&ph_lg,   h_lg);
        cudaGetSymbolAddress((void**)&ph_x2,   h_x2);
        cudaGetSymbolAddress((void**)&ph_ffh,  h_ffh);
        cudaGetSymbolAddress((void**)&ph_hin,  h_hin);
        cudaGetSymbolAddress((void**)&ph_lgin, h_lgin);
        cudaGetSymbolAddress((void**)&ph_w1,   h_w1);
        cudaGetSymbolAddress((void**)&ph_w2,   h_w2);
        cudaGetSymbolAddress((void**)&ph_uw,   h_uw);
        cudaGetSymbolAddress((void**)&ph_w3,   h_w3);
        cudaGetSymbolAddress((void**)&ph_w4,   h_w4);
        cudaGetSymbolAddress((void**)&ph_hw,   h_hw);
        cudaGetSymbolAddress((void**)&ph_vw,   h_vw);
        cudaFuncSetAttribute(tgemm<0,0>, cudaFuncAttributeMaxDynamicSharedMemorySize, T_SMEM);
        cudaFuncSetAttribute(tgemm<0,1>, cudaFuncAttributeMaxDynamicSharedMemorySize, T_SMEM);
        cudaFuncSetAttribute(tgemm<1,0>, cudaFuncAttributeMaxDynamicSharedMemorySize, T_SMEM);
        cudaFuncSetAttribute(tgemm<1,1>, cudaFuncAttributeMaxDynamicSharedMemorySize, T_SMEM);
        cudaFuncSetAttribute(tgemm<2,2>, cudaFuncAttributeMaxDynamicSharedMemorySize, T_SMEM);
        cudaFuncSetAttribute(tgemm<3,0>, cudaFuncAttributeMaxDynamicSharedMemorySize, T_SMEM);
        cudaFuncSetAttribute(attn_kernel, cudaFuncAttributeMaxDynamicSharedMemorySize, A_SMEM);
        init_done = true;
    }

    float* out_x = (float*)d_out;
    float* out_hidden = out_x + (size_t)NTOK * TE;
    float* out_stack  = out_hidden + (size_t)NTOK * TDH;

    // single batched convert (6 weights + x_in) + hidden weight pack
    cvt_all_kernel<<<(SEGT + 255)/256, 256>>>(in_proj_w, out_proj_w, U_w,
                                              ffi_w, ffo_w, V_w, x_in);
    pack_hw<<<(256*448 + 255)/256, 256>>>(W_w, R_w, P_w, W_b, R_b, P_b, ph_hw, p_hb);

    // 1) qkv (fp16 out)
    tgemm<0,1><<<dim3(12,64),256,T_SMEM>>>(ph_xin, ph_w1,
        in_proj_b, nullptr, nullptr, ph_qkv, NTOK, 1536, 512);
    // 2) flash attention (128 q-rows per CTA, per-warp masked-tile skip)
    attn_kernel<<<dim3(8,64),256,A_SMEM>>>(ph_qkv, ph_ao);
    // 3) out projection
    tgemm<0,0><<<dim3(4,64),256,T_SMEM>>>(ph_ao, ph_w2,
        out_proj_b, nullptr, p_proj, nullptr, NTOK, 512, 512);
    // 4) x1 = nonsat(LN(x_in + proj)); also scatters fp16 x1 into hin + lgin
    add_ln_kernel<true><<<NTOK,256>>>(x_in, p_proj, ln1_g, ln1_b, p_x1, ph_hin, ph_lgin);
    // 5) hidden via HMMA (pack only non-x1 segments)
    pack_hidden_in<<<(NTOK*192 + 255)/256, 256>>>(hidden_prev, stack_prev, ph_hin);
    tgemm<1,0><<<dim3(2,64),256,T_SMEM>>>(ph_hin, ph_hw,
        p_hb, nullptr, out_hidden, nullptr, NTOK, 256, 896);
    // 6) logits via HMMA (pack only hidden segment)
    pack_logits_in<<<(NTOK*128 + 255)/256, 256>>>(out_hidden, ph_lgin);
    tgemm<3,0><<<dim3(1,64),256,T_SMEM>>>(ph_lgin, ph_vw,
        nullptr, nullptr, p_lg, nullptr, NTOK, 128, 768);
    // 7) softmax (fp16 out)
    softmax128_kernel<<<NTOK/8,256>>>(p_lg, ph_lg);
    // 8) x2 = 0.5*(x1 + sm @ U_w.T)   (fp32 + fp16 out)
    tgemm<2,2><<<dim3(4,64),256,T_SMEM>>>(ph_lg, ph_uw,
        nullptr, p_x1, p_x2, ph_x2, NTOK, 512, 128);
    // 9) stack
    stack_kernel<<<NTOK,128>>>(out_hidden, stack_prev, A_w, A_b, D_w, D_b, out_stack);
    // 10) ff hidden (fp16 out)
    tgemm<1,1><<<dim3(16,64),256,T_SMEM>>>(ph_x2, ph_w3,
        ffi_b, nullptr, nullptr, ph_ffh, NTOK, 2048, 512);
    // 11) ff out
    tgemm<0,0><<<dim3(4,64),256,T_SMEM>>>(ph_ffh, ph_w4,
        ffo_b, nullptr, p_ffo, nullptr, NTOK, 512, 2048);
    // 12) x_out
    add_ln_kernel<false><<<NTOK,256>>>(p_x2, p_ffo, ln2_g, ln2_b, out_x, nullptr, nullptr);
}